// round 12
// baseline (speedup 1.0000x reference)
#include <cuda_runtime.h>
#include <cuda_fp16.h>
#include <cstdint>
#include <cstddef>

#define S_TOK 8192
#define DIM 1280
#define DIM3 3840
#define NH 16
#define DH 80
#define NSEG 8
#define SEGLEN 1024
#define GK 1280           // GEMM K (halves)
#define GBK 32            // GEMM k per tile (halves)
#define GNT (GK / GBK)    // 40 k-tiles

// Scratch (device globals: allocation-free per harness rules)
__device__ __half g_qkv16[S_TOK * DIM3];  // qkv result (fp16)
__device__ __half g_q16[S_TOK * DIM];     // roped Q * scale (fp16)
__device__ __half g_k16[S_TOK * DIM];     // roped K (fp16)
__device__ __half g_attn16[S_TOK * DIM];  // attention out (fp16)
__device__ __half g_hs16[S_TOK * DIM];    // fp16 hidden_states
__device__ __half g_wq16[DIM3 * DIM];     // fp16 qkv_w
__device__ __half g_wp16[DIM * DIM];      // fp16 proj_w

// ---------------------------------------------------------------------------
// helpers (baseline PTX, no arch-specific features)
// ---------------------------------------------------------------------------
__device__ __forceinline__ void mma_f16(float* c, const uint32_t* a, const uint32_t* b) {
    asm volatile(
        "mma.sync.aligned.m16n8k16.row.col.f32.f16.f16.f32 "
        "{%0,%1,%2,%3}, {%4,%5,%6,%7}, {%8,%9}, {%0,%1,%2,%3};"
        : "+f"(c[0]), "+f"(c[1]), "+f"(c[2]), "+f"(c[3])
        : "r"(a[0]), "r"(a[1]), "r"(a[2]), "r"(a[3]), "r"(b[0]), "r"(b[1]));
}

__device__ __forceinline__ void ldsm_x4(uint32_t* r, uint32_t addr) {
    asm volatile(
        "ldmatrix.sync.aligned.m8n8.x4.shared.b16 {%0,%1,%2,%3}, [%4];"
        : "=r"(r[0]), "=r"(r[1]), "=r"(r[2]), "=r"(r[3]) : "r"(addr));
}

__device__ __forceinline__ void ldsm_x4_t(uint32_t* r, uint32_t addr) {
    asm volatile(
        "ldmatrix.sync.aligned.m8n8.x4.trans.shared.b16 {%0,%1,%2,%3}, [%4];"
        : "=r"(r[0]), "=r"(r[1]), "=r"(r[2]), "=r"(r[3]) : "r"(addr));
}

__device__ __forceinline__ uint32_t smem_addr_u32(const void* p) {
    return (uint32_t)__cvta_generic_to_shared(p);
}

__device__ __forceinline__ uint32_t pack_h2(float a, float b) {
    __half2 h = __floats2half2_rn(a, b);
    return *(uint32_t*)&h;
}

// ---------------------------------------------------------------------------
// fp32 -> fp16 convert (vectorized)
// ---------------------------------------------------------------------------
__global__ void to_f16_kernel(const float4* __restrict__ src,
                              __half* __restrict__ dst, int n4)
{
    int i = blockIdx.x * blockDim.x + threadIdx.x;
    if (i >= n4) return;
    float4 v = src[i];
    uint2 o;
    o.x = pack_h2(v.x, v.y);
    o.y = pack_h2(v.z, v.w);
    *(uint2*)(dst + (size_t)i * 4) = o;
}

// ---------------------------------------------------------------------------
// fp16 tensor-core GEMM (NT): C[M,N] = A[M,1280] @ B[N,1280]^T + bias[N]
// BM=BN=128, BK=32 halves, 128 threads = 4 warps (2Mx2N), warp tile 64x64.
// 4-stage cp.async pipeline; fragments via ldmatrix.
// ---------------------------------------------------------------------------
#define GLDH 40                            // smem row stride in halves
#define ROWB (GLDH * 2)                    // 80 bytes per row
#define STAGES 4
#define STAGE_BYTES (128 * ROWB)           // 10240 per operand
#define GEMM_SMEM (STAGES * 2 * STAGE_BYTES)  // 81920

__global__ __launch_bounds__(128, 2) void gemm_f16_pipe(
    const __half* __restrict__ A, const __half* __restrict__ B,
    const float* __restrict__ bias, void* __restrict__ Cout,
    int N, int half_out)
{
    extern __shared__ __half smp[];
    __half* As = smp;                                 // [STAGES][128][GLDH]
    __half* Bs = smp + STAGES * 128 * GLDH;

    const int tid = threadIdx.x;
    const int lane = tid & 31;
    const int wid = tid >> 5;
    const int wm = (wid & 1) * 64;
    const int wn = (wid >> 1) * 64;
    const int bm = blockIdx.y * 128;
    const int bn = blockIdx.x * 128;

    // global load: each thread owns one row (32 halves) of A and of B per tile
    const __half* Ag = A + (size_t)(bm + tid) * GK;
    const __half* Bg = B + (size_t)(bn + tid) * GK;

    const uint32_t As_base = smem_addr_u32(As);
    const uint32_t Bs_base = smem_addr_u32(Bs);
    const uint32_t sA = As_base + (uint32_t)tid * ROWB;
    const uint32_t sB = Bs_base + (uint32_t)tid * ROWB;

    // ldmatrix lane offsets (bytes within a stage)
    const uint32_t a_off = ((uint32_t)(wm + (lane & 15)) * GLDH +
                            ((lane >> 4) << 3)) * 2;
    const uint32_t b_off = ((uint32_t)(wn + (lane & 7) + ((lane >> 4) << 3)) * GLDH +
                            (((lane >> 3) & 1) << 3)) * 2;

    float acc[4][8][4];
#pragma unroll
    for (int i = 0; i < 4; i++)
#pragma unroll
        for (int j = 0; j < 8; j++)
#pragma unroll
            for (int c = 0; c < 4; c++) acc[i][j][c] = 0.f;

#define ISSUE(ktv) do {                                                      \
    const int _st = (ktv) % STAGES;                                          \
    const __half* _ap = Ag + (ktv) * GBK;                                    \
    const __half* _bp = Bg + (ktv) * GBK;                                    \
    uint32_t _da = sA + _st * STAGE_BYTES;                                   \
    uint32_t _db = sB + _st * STAGE_BYTES;                                   \
    asm volatile(                                                            \
        "cp.async.cg.shared.global [%0], [%1], 16;\n\t"                      \
        "cp.async.cg.shared.global [%2], [%3], 16;\n\t"                      \
        "cp.async.cg.shared.global [%4], [%5], 16;\n\t"                      \
        "cp.async.cg.shared.global [%6], [%7], 16;\n\t"                      \
        :: "r"(_da), "l"(_ap), "r"(_da + 16), "l"(_ap + 8),                  \
           "r"(_da + 32), "l"(_ap + 16), "r"(_da + 48), "l"(_ap + 24)        \
        : "memory");                                                         \
    asm volatile(                                                            \
        "cp.async.cg.shared.global [%0], [%1], 16;\n\t"                      \
        "cp.async.cg.shared.global [%2], [%3], 16;\n\t"                      \
        "cp.async.cg.shared.global [%4], [%5], 16;\n\t"                      \
        "cp.async.cg.shared.global [%6], [%7], 16;\n\t"                      \
        "cp.async.commit_group;"                                             \
        :: "r"(_db), "l"(_bp), "r"(_db + 16), "l"(_bp + 8),                  \
           "r"(_db + 32), "l"(_bp + 16), "r"(_db + 48), "l"(_bp + 24)        \
        : "memory");                                                         \
} while (0)

#pragma unroll
    for (int s = 0; s < STAGES - 1; s++) ISSUE(s);

    for (int kt = 0; kt < GNT; ++kt) {
        const int st = kt % STAGES;
        asm volatile("cp.async.wait_group %0;" :: "n"(STAGES - 2));
        __syncthreads();
        if (kt + STAGES - 1 < GNT) ISSUE(kt + STAGES - 1);

        const uint32_t a_base = As_base + st * STAGE_BYTES + a_off;
        const uint32_t b_base = Bs_base + st * STAGE_BYTES + b_off;
#pragma unroll
        for (int ks = 0; ks < 2; ++ks) {
            const uint32_t kcb = ks * 32;   // 16 halves per k-step
            uint32_t af[4][4], bq[4][4];
#pragma unroll
            for (int i = 0; i < 4; i++)
                ldsm_x4(af[i], a_base + (uint32_t)(i * 16 * ROWB) + kcb);
#pragma unroll
            for (int jp = 0; jp < 4; jp++)
                ldsm_x4(bq[jp], b_base + (uint32_t)(jp * 16 * ROWB) + kcb);
#pragma unroll
            for (int i = 0; i < 4; i++)
#pragma unroll
                for (int j = 0; j < 8; j++)
                    mma_f16(acc[i][j], af[i], &bq[j >> 1][(j & 1) * 2]);
        }
    }
#undef ISSUE

    const int r = lane >> 2;
    const int cq = lane & 3;
#pragma unroll
    for (int i = 0; i < 4; i++) {
        const int row0 = bm + wm + i * 16 + r;
#pragma unroll
        for (int j = 0; j < 8; j++) {
            const int col = bn + wn + j * 8 + cq * 2;
            const float b0 = bias[col], b1 = bias[col + 1];
            if (half_out) {
                __half* C16 = (__half*)Cout;
                *(uint32_t*)(C16 + (size_t)row0 * N + col) =
                    pack_h2(acc[i][j][0] + b0, acc[i][j][1] + b1);
                *(uint32_t*)(C16 + (size_t)(row0 + 8) * N + col) =
                    pack_h2(acc[i][j][2] + b0, acc[i][j][3] + b1);
            } else {
                float* C32 = (float*)Cout;
                float2 v;
                v.x = acc[i][j][0] + b0; v.y = acc[i][j][1] + b1;
                *(float2*)(C32 + (size_t)row0 * N + col) = v;
                v.x = acc[i][j][2] + b0; v.y = acc[i][j][3] + b1;
                *(float2*)(C32 + (size_t)(row0 + 8) * N + col) = v;
            }
        }
    }
}

// ---------------------------------------------------------------------------
// RoPE on fp16 qkv: q <- (q*cos + rot(q)*sin)*scale, k <- k*cos + rot(k)*sin
// ---------------------------------------------------------------------------
__global__ void rope16_kernel(const float* __restrict__ cosp,
                              const float* __restrict__ sinp)
{
    int idx = blockIdx.x * blockDim.x + threadIdx.x;
    if (idx >= S_TOK * DIM) return;
    int s = idx / DIM;
    int c = idx - s * DIM;
    int d = c % DH;
    float cv = cosp[s * DH + d];
    float sv = sinp[s * DH + d];
    const __half* row = g_qkv16 + (size_t)s * DIM3;
    float qv = __half2float(row[c]);
    float kv = __half2float(row[DIM + c]);
    float qr, kr;
    if (d < DH / 2) {
        qr = -__half2float(row[c + DH / 2]);
        kr = -__half2float(row[DIM + c + DH / 2]);
    } else {
        qr = __half2float(row[c - DH / 2]);
        kr = __half2float(row[DIM + c - DH / 2]);
    }
    const float scale = 0.11180339887498949f; // 1/sqrt(80)
    g_q16[idx] = __float2half_rn(fmaf(qv, cv, qr * sv) * scale);
    g_k16[idx] = __float2half_rn(fmaf(kv, cv, kr * sv));
}

// ---------------------------------------------------------------------------
// fp16 tensor-core flash attention. Block = 128 Q rows x (seg, head);
// 8 warps x 16 rows. Double-buffered cp.async K/V; K via ldmatrix,
// V via ldmatrix.trans; P packs locally into A-frags (no shuffles).
// ---------------------------------------------------------------------------
#define KVLD 88                            // K/V smem row stride (halves)
#define KVBUF_BYTES (64 * KVLD * 2)        // 11264
#define ATT_SMEM (4 * KVBUF_BYTES)         // 45056

__global__ __launch_bounds__(256, 2) void attn_f16()
{
    extern __shared__ __half asmem[];
    const uint32_t Ks_base = smem_addr_u32(asmem);
    const uint32_t Vs_base = Ks_base + 2 * KVBUF_BYTES;

    const int tid = threadIdx.x;
    const int lane = tid & 31;
    const int w = tid >> 5;
    const int r = lane >> 2;
    const int cq = lane & 3;

    const int qb = blockIdx.x;
    const int h = blockIdx.y;
    const int seg = blockIdx.z;
    const int qrow = seg * SEGLEN + qb * 128 + w * 16;
    const int hoff = h * DH;

#define AISSUE(kvtv, buf) do {                                               \
    const int _tb = seg * SEGLEN + (kvtv) * 64;                              \
    for (int _c = tid; _c < 640; _c += 256) {                                \
        int _row = _c / 10, _c16 = _c - _row * 10;                           \
        uint32_t _kd = Ks_base + (buf) * KVBUF_BYTES + _row * (KVLD * 2) + _c16 * 16; \
        uint32_t _vd = Vs_base + (buf) * KVBUF_BYTES + _row * (KVLD * 2) + _c16 * 16; \
        const __half* _kp = g_k16 + (size_t)(_tb + _row) * DIM + hoff + _c16 * 8; \
        const __half* _vp = g_qkv16 + (size_t)(_tb + _row) * DIM3 + 2 * DIM + hoff + _c16 * 8; \
        asm volatile(                                                        \
            "cp.async.cg.shared.global [%0], [%1], 16;\n\t"                  \
            "cp.async.cg.shared.global [%2], [%3], 16;\n\t"                  \
            :: "r"(_kd), "l"(_kp), "r"(_vd), "l"(_vp) : "memory");           \
    }                                                                        \
    asm volatile("cp.async.commit_group;" ::: "memory");                     \
} while (0)

    // Q fragments: 5 k-steps of 16 halves
    uint32_t qa[5][4];
    {
        const __half* Qb = g_q16 + (size_t)qrow * DIM + hoff;
#pragma unroll
        for (int ks = 0; ks < 5; ks++) {
            qa[ks][0] = *(const uint32_t*)(Qb + (size_t)r * DIM + ks * 16 + 2 * cq);
            qa[ks][1] = *(const uint32_t*)(Qb + (size_t)(r + 8) * DIM + ks * 16 + 2 * cq);
            qa[ks][2] = *(const uint32_t*)(Qb + (size_t)r * DIM + ks * 16 + 8 + 2 * cq);
            qa[ks][3] = *(const uint32_t*)(Qb + (size_t)(r + 8) * DIM + ks * 16 + 8 + 2 * cq);
        }
    }

    float m0 = -1e30f, m1 = -1e30f, l0 = 0.f, l1 = 0.f;
    float oacc[10][4];
#pragma unroll
    for (int v = 0; v < 10; v++)
#pragma unroll
        for (int c = 0; c < 4; c++) oacc[v][c] = 0.f;

    // ldmatrix lane offsets (bytes within a buffer)
    const uint32_t kb_off = ((uint32_t)((lane & 7) + ((lane >> 4) << 3)) * KVLD +
                            (((lane >> 3) & 1) << 3)) * 2;
    const uint32_t vb_off = ((uint32_t)((lane & 7) + (((lane >> 3) & 1) << 3)) * KVLD +
                            (((lane >> 4) & 1) << 3)) * 2;

    AISSUE(0, 0);

    for (int kvt = 0; kvt < 16; kvt++) {
        const int buf = kvt & 1;
        asm volatile("cp.async.wait_group 0;" ::: "memory");
        __syncthreads();
        if (kvt + 1 < 16) AISSUE(kvt + 1, buf ^ 1);

        const uint32_t kbase = Ks_base + buf * KVBUF_BYTES + kb_off;
        const uint32_t vbase = Vs_base + buf * KVBUF_BYTES + vb_off;

        // S = Q K^T : per k-step, batch 4 LDSM then 8 MMA
        float sc[8][4];
#pragma unroll
        for (int j = 0; j < 8; j++)
#pragma unroll
            for (int c = 0; c < 4; c++) sc[j][c] = 0.f;

#pragma unroll
        for (int ks = 0; ks < 5; ks++) {
            uint32_t bq[4][4];
#pragma unroll
            for (int jp = 0; jp < 4; jp++)
                ldsm_x4(bq[jp], kbase + (uint32_t)(jp * 16 * KVLD * 2) +
                                (uint32_t)(ks * 32));
#pragma unroll
            for (int jp = 0; jp < 4; jp++) {
                mma_f16(sc[jp * 2], qa[ks], &bq[jp][0]);
                mma_f16(sc[jp * 2 + 1], qa[ks], &bq[jp][2]);
            }
        }

        // Online softmax (C-frag layout: rows r / r+8)
        float mx0 = -1e30f, mx1 = -1e30f;
#pragma unroll
        for (int j = 0; j < 8; j++) {
            mx0 = fmaxf(mx0, fmaxf(sc[j][0], sc[j][1]));
            mx1 = fmaxf(mx1, fmaxf(sc[j][2], sc[j][3]));
        }
        mx0 = fmaxf(mx0, __shfl_xor_sync(0xffffffffu, mx0, 1));
        mx0 = fmaxf(mx0, __shfl_xor_sync(0xffffffffu, mx0, 2));
        mx1 = fmaxf(mx1, __shfl_xor_sync(0xffffffffu, mx1, 1));
        mx1 = fmaxf(mx1, __shfl_xor_sync(0xffffffffu, mx1, 2));
        const float nm0 = fmaxf(m0, mx0);
        const float nm1 = fmaxf(m1, mx1);
        const float corr0 = __expf(m0 - nm0);
        const float corr1 = __expf(m1 - nm1);
        m0 = nm0; m1 = nm1;

        float sum0 = 0.f, sum1 = 0.f;
#pragma unroll
        for (int j = 0; j < 8; j++) {
            sc[j][0] = __expf(sc[j][0] - nm0);
            sc[j][1] = __expf(sc[j][1] - nm0);
            sc[j][2] = __expf(sc[j][2] - nm1);
            sc[j][3] = __expf(sc[j][3] - nm1);
            sum0 += sc[j][0] + sc[j][1];
            sum1 += sc[j][2] + sc[j][3];
        }
        sum0 += __shfl_xor_sync(0xffffffffu, sum0, 1);
        sum0 += __shfl_xor_sync(0xffffffffu, sum0, 2);
        sum1 += __shfl_xor_sync(0xffffffffu, sum1, 1);
        sum1 += __shfl_xor_sync(0xffffffffu, sum1, 2);
        l0 = l0 * corr0 + sum0;
        l1 = l1 * corr1 + sum1;

#pragma unroll
        for (int v = 0; v < 10; v++) {
            oacc[v][0] *= corr0; oacc[v][1] *= corr0;
            oacc[v][2] *= corr1; oacc[v][3] *= corr1;
        }

        // O += P V : P packs locally (C-frag -> fp16 A-frag is lane-local)
#pragma unroll
        for (int t = 0; t < 4; t++) {
            uint32_t pa[4];
            pa[0] = pack_h2(sc[2 * t][0], sc[2 * t][1]);
            pa[1] = pack_h2(sc[2 * t][2], sc[2 * t][3]);
            pa[2] = pack_h2(sc[2 * t + 1][0], sc[2 * t + 1][1]);
            pa[3] = pack_h2(sc[2 * t + 1][2], sc[2 * t + 1][3]);
#pragma unroll
            for (int vp = 0; vp < 5; vp++) {
                uint32_t bv[4];
                ldsm_x4_t(bv, vbase + (uint32_t)(t * 16 * KVLD * 2) +
                              (uint32_t)(vp * 32));
                mma_f16(oacc[2 * vp], pa, &bv[0]);
                mma_f16(oacc[2 * vp + 1], pa, &bv[2]);
            }
        }
    }
#undef AISSUE

    // Epilogue: fp16 out (proj GEMM input)
    const float inv0 = 1.f / l0;
    const float inv1 = 1.f / l1;
    __half* O0 = g_attn16 + (size_t)(qrow + r) * DIM + hoff;
    __half* O1 = g_attn16 + (size_t)(qrow + r + 8) * DIM + hoff;
#pragma unroll
    for (int v = 0; v < 10; v++) {
        *(uint32_t*)(O0 + v * 8 + 2 * cq) =
            pack_h2(oacc[v][0] * inv0, oacc[v][1] * inv0);
        *(uint32_t*)(O1 + v * 8 + 2 * cq) =
            pack_h2(oacc[v][2] * inv1, oacc[v][3] * inv1);
    }
}

// ---------------------------------------------------------------------------
extern "C" void kernel_launch(void* const* d_in, const int* in_sizes, int n_in,
                              void* d_out, int out_size)
{
    const float* hs     = (const float*)d_in[0];
    const float* cosp   = (const float*)d_in[1];
    const float* sinp   = (const float*)d_in[2];
    const float* qkv_w  = (const float*)d_in[3];
    const float* qkv_b  = (const float*)d_in[4];
    const float* proj_w = (const float*)d_in[5];
    const float* proj_b = (const float*)d_in[6];
    float* out = (float*)d_out;

    __half *qkv_p, *attn_p, *hs_p, *wq_p, *wp_p;
    cudaGetSymbolAddress((void**)&qkv_p, g_qkv16);
    cudaGetSymbolAddress((void**)&attn_p, g_attn16);
    cudaGetSymbolAddress((void**)&hs_p, g_hs16);
    cudaGetSymbolAddress((void**)&wq_p, g_wq16);
    cudaGetSymbolAddress((void**)&wp_p, g_wp16);

    cudaFuncSetAttribute(gemm_f16_pipe,
                         cudaFuncAttributeMaxDynamicSharedMemorySize, GEMM_SMEM);
    cudaFuncSetAttribute(attn_f16,
                         cudaFuncAttributeMaxDynamicSharedMemorySize, ATT_SMEM);

    // 0) Convert GEMM inputs to fp16
    {
        int n4 = S_TOK * DIM / 4;
        to_f16_kernel<<<(n4 + 255) / 256, 256>>>((const float4*)hs, hs_p, n4);
        n4 = DIM3 * DIM / 4;
        to_f16_kernel<<<(n4 + 255) / 256, 256>>>((const float4*)qkv_w, wq_p, n4);
        n4 = DIM * DIM / 4;
        to_f16_kernel<<<(n4 + 255) / 256, 256>>>((const float4*)proj_w, wp_p, n4);
    }

    // 1) QKV GEMM + bias (fp16 tensor cores), fp16 output
    dim3 g1(DIM3 / 128, S_TOK / 128);
    gemm_f16_pipe<<<g1, 128, GEMM_SMEM>>>(hs_p, wq_p, qkv_b, qkv_p, DIM3, 1);

    // 2) RoPE (folds softmax scale into Q)
    int total = S_TOK * DIM;
    rope16_kernel<<<(total + 255) / 256, 256>>>(cosp, sinp);

    // 3) fp16 tensor-core flash attention
    dim3 g2(SEGLEN / 128, NH, NSEG);
    attn_f16<<<g2, 256, ATT_SMEM>>>();

    // 4) Output projection + bias (fp32 output)
    dim3 g3(DIM / 128, S_TOK / 128);
    gemm_f16_pipe<<<g3, 128, GEMM_SMEM>>>(attn_p, wp_p, proj_b, out, DIM, 0);
}

// round 13
// speedup vs baseline: 1.1360x; 1.1360x over previous
#include <cuda_runtime.h>
#include <cuda_fp16.h>
#include <cstdint>
#include <cstddef>

#define S_TOK 8192
#define DIM 1280
#define DIM3 3840
#define NH 16
#define DH 80
#define NSEG 8
#define SEGLEN 1024
#define GK 1280           // GEMM K (halves)
#define GBK 64            // GEMM k per tile (halves)
#define GNT (GK / GBK)    // 20 k-tiles

// Scratch (device globals: allocation-free per harness rules)
__device__ __half g_qkv16[S_TOK * DIM3];  // qkv result (fp16)
__device__ __half g_q16[S_TOK * DIM];     // roped Q * scale (fp16)
__device__ __half g_k16[S_TOK * DIM];     // roped K (fp16)
__device__ __half g_attn16[S_TOK * DIM];  // attention out (fp16)
__device__ __half g_hs16[S_TOK * DIM];    // fp16 hidden_states
__device__ __half g_wq16[DIM3 * DIM];     // fp16 qkv_w
__device__ __half g_wp16[DIM * DIM];      // fp16 proj_w

// ---------------------------------------------------------------------------
// helpers (baseline PTX, no arch-specific features)
// ---------------------------------------------------------------------------
__device__ __forceinline__ void mma_f16(float* c, const uint32_t* a, const uint32_t* b) {
    asm volatile(
        "mma.sync.aligned.m16n8k16.row.col.f32.f16.f16.f32 "
        "{%0,%1,%2,%3}, {%4,%5,%6,%7}, {%8,%9}, {%0,%1,%2,%3};"
        : "+f"(c[0]), "+f"(c[1]), "+f"(c[2]), "+f"(c[3])
        : "r"(a[0]), "r"(a[1]), "r"(a[2]), "r"(a[3]), "r"(b[0]), "r"(b[1]));
}

__device__ __forceinline__ void ldsm_x4(uint32_t* r, uint32_t addr) {
    asm volatile(
        "ldmatrix.sync.aligned.m8n8.x4.shared.b16 {%0,%1,%2,%3}, [%4];"
        : "=r"(r[0]), "=r"(r[1]), "=r"(r[2]), "=r"(r[3]) : "r"(addr));
}

__device__ __forceinline__ void ldsm_x4_t(uint32_t* r, uint32_t addr) {
    asm volatile(
        "ldmatrix.sync.aligned.m8n8.x4.trans.shared.b16 {%0,%1,%2,%3}, [%4];"
        : "=r"(r[0]), "=r"(r[1]), "=r"(r[2]), "=r"(r[3]) : "r"(addr));
}

__device__ __forceinline__ uint32_t smem_addr_u32(const void* p) {
    return (uint32_t)__cvta_generic_to_shared(p);
}

__device__ __forceinline__ uint32_t pack_h2(float a, float b) {
    __half2 h = __floats2half2_rn(a, b);
    return *(uint32_t*)&h;
}

// ---------------------------------------------------------------------------
// fp32 -> fp16 convert (vectorized)
// ---------------------------------------------------------------------------
__global__ void to_f16_kernel(const float4* __restrict__ src,
                              __half* __restrict__ dst, int n4)
{
    int i = blockIdx.x * blockDim.x + threadIdx.x;
    if (i >= n4) return;
    float4 v = src[i];
    uint2 o;
    o.x = pack_h2(v.x, v.y);
    o.y = pack_h2(v.z, v.w);
    *(uint2*)(dst + (size_t)i * 4) = o;
}

// ---------------------------------------------------------------------------
// fp16 tensor-core GEMM (NT): C[M,N] = A[M,1280] @ B[N,1280]^T + bias[N]
// BM=BN=128, BK=64 halves, 256 threads = 8 warps (2Mx4N), warp tile 64x32.
// Double-buffered cp.async (full-tile depth); fragments via ldmatrix.
// ---------------------------------------------------------------------------
#define GLDH 72                            // smem row stride in halves
#define ROWB (GLDH * 2)                    // 144 bytes per row
#define STAGES 2
#define STAGE_BYTES (128 * ROWB)           // 18432 per operand
#define GEMM_SMEM (STAGES * 2 * STAGE_BYTES)  // 73728

__global__ __launch_bounds__(256, 2) void gemm_f16_pipe(
    const __half* __restrict__ A, const __half* __restrict__ B,
    const float* __restrict__ bias, void* __restrict__ Cout,
    int N, int half_out)
{
    extern __shared__ __half smp[];
    __half* As = smp;                                 // [STAGES][128][GLDH]
    __half* Bs = smp + STAGES * 128 * GLDH;

    const int tid = threadIdx.x;
    const int lane = tid & 31;
    const int wid = tid >> 5;
    const int wm = (wid & 1) * 64;
    const int wn = (wid >> 1) * 32;
    const int bm = blockIdx.y * 128;
    const int bn = blockIdx.x * 128;

    // global load: 2 threads per row, each 32 halves (64 B)
    const int lrow = tid >> 1;            // 0..127
    const int lhh = (tid & 1) * 32;       // halves 0 or 32
    const __half* Ag = A + (size_t)(bm + lrow) * GK + lhh;
    const __half* Bg = B + (size_t)(bn + lrow) * GK + lhh;

    const uint32_t As_base = smem_addr_u32(As);
    const uint32_t Bs_base = smem_addr_u32(Bs);
    const uint32_t sA = As_base + (uint32_t)lrow * ROWB + (uint32_t)(tid & 1) * 64;
    const uint32_t sB = Bs_base + (uint32_t)lrow * ROWB + (uint32_t)(tid & 1) * 64;

    // ldmatrix lane offsets (bytes within a stage)
    const uint32_t a_off = ((uint32_t)(wm + (lane & 15)) * GLDH +
                            ((lane >> 4) << 3)) * 2;
    const uint32_t b_off = ((uint32_t)(wn + (lane & 7) + ((lane >> 4) << 3)) * GLDH +
                            (((lane >> 3) & 1) << 3)) * 2;

    float acc[4][4][4];
#pragma unroll
    for (int i = 0; i < 4; i++)
#pragma unroll
        for (int j = 0; j < 4; j++)
#pragma unroll
            for (int c = 0; c < 4; c++) acc[i][j][c] = 0.f;

#define ISSUE(ktv) do {                                                      \
    const int _st = (ktv) % STAGES;                                          \
    const __half* _ap = Ag + (ktv) * GBK;                                    \
    const __half* _bp = Bg + (ktv) * GBK;                                    \
    uint32_t _da = sA + _st * STAGE_BYTES;                                   \
    uint32_t _db = sB + _st * STAGE_BYTES;                                   \
    asm volatile(                                                            \
        "cp.async.cg.shared.global [%0], [%1], 16;\n\t"                      \
        "cp.async.cg.shared.global [%2], [%3], 16;\n\t"                      \
        "cp.async.cg.shared.global [%4], [%5], 16;\n\t"                      \
        "cp.async.cg.shared.global [%6], [%7], 16;\n\t"                      \
        :: "r"(_da), "l"(_ap), "r"(_da + 16), "l"(_ap + 8),                  \
           "r"(_da + 32), "l"(_ap + 16), "r"(_da + 48), "l"(_ap + 24)        \
        : "memory");                                                         \
    asm volatile(                                                            \
        "cp.async.cg.shared.global [%0], [%1], 16;\n\t"                      \
        "cp.async.cg.shared.global [%2], [%3], 16;\n\t"                      \
        "cp.async.cg.shared.global [%4], [%5], 16;\n\t"                      \
        "cp.async.cg.shared.global [%6], [%7], 16;\n\t"                      \
        "cp.async.commit_group;"                                             \
        :: "r"(_db), "l"(_bp), "r"(_db + 16), "l"(_bp + 8),                  \
           "r"(_db + 32), "l"(_bp + 16), "r"(_db + 48), "l"(_bp + 24)        \
        : "memory");                                                         \
} while (0)

    ISSUE(0);

    for (int kt = 0; kt < GNT; ++kt) {
        const int st = kt % STAGES;
        asm volatile("cp.async.wait_group 0;" ::: "memory");
        __syncthreads();
        if (kt + 1 < GNT) ISSUE(kt + 1);

        const uint32_t a_base = As_base + st * STAGE_BYTES + a_off;
        const uint32_t b_base = Bs_base + st * STAGE_BYTES + b_off;
#pragma unroll
        for (int ks = 0; ks < 4; ++ks) {
            const uint32_t kcb = ks * 32;   // 16 halves per k-step
            uint32_t af[4][4], bq[2][4];
#pragma unroll
            for (int i = 0; i < 4; i++)
                ldsm_x4(af[i], a_base + (uint32_t)(i * 16 * ROWB) + kcb);
#pragma unroll
            for (int jp = 0; jp < 2; jp++)
                ldsm_x4(bq[jp], b_base + (uint32_t)(jp * 16 * ROWB) + kcb);
#pragma unroll
            for (int i = 0; i < 4; i++)
#pragma unroll
                for (int j = 0; j < 4; j++)
                    mma_f16(acc[i][j], af[i], &bq[j >> 1][(j & 1) * 2]);
        }
    }
#undef ISSUE

    const int r = lane >> 2;
    const int cq = lane & 3;
#pragma unroll
    for (int i = 0; i < 4; i++) {
        const int row0 = bm + wm + i * 16 + r;
#pragma unroll
        for (int j = 0; j < 4; j++) {
            const int col = bn + wn + j * 8 + cq * 2;
            const float b0 = bias[col], b1 = bias[col + 1];
            if (half_out) {
                __half* C16 = (__half*)Cout;
                *(uint32_t*)(C16 + (size_t)row0 * N + col) =
                    pack_h2(acc[i][j][0] + b0, acc[i][j][1] + b1);
                *(uint32_t*)(C16 + (size_t)(row0 + 8) * N + col) =
                    pack_h2(acc[i][j][2] + b0, acc[i][j][3] + b1);
            } else {
                float* C32 = (float*)Cout;
                float2 v;
                v.x = acc[i][j][0] + b0; v.y = acc[i][j][1] + b1;
                *(float2*)(C32 + (size_t)row0 * N + col) = v;
                v.x = acc[i][j][2] + b0; v.y = acc[i][j][3] + b1;
                *(float2*)(C32 + (size_t)(row0 + 8) * N + col) = v;
            }
        }
    }
}

// ---------------------------------------------------------------------------
// RoPE on fp16 qkv: q <- (q*cos + rot(q)*sin)*scale, k <- k*cos + rot(k)*sin
// ---------------------------------------------------------------------------
__global__ void rope16_kernel(const float* __restrict__ cosp,
                              const float* __restrict__ sinp)
{
    int idx = blockIdx.x * blockDim.x + threadIdx.x;
    if (idx >= S_TOK * DIM) return;
    int s = idx / DIM;
    int c = idx - s * DIM;
    int d = c % DH;
    float cv = cosp[s * DH + d];
    float sv = sinp[s * DH + d];
    const __half* row = g_qkv16 + (size_t)s * DIM3;
    float qv = __half2float(row[c]);
    float kv = __half2float(row[DIM + c]);
    float qr, kr;
    if (d < DH / 2) {
        qr = -__half2float(row[c + DH / 2]);
        kr = -__half2float(row[DIM + c + DH / 2]);
    } else {
        qr = __half2float(row[c - DH / 2]);
        kr = __half2float(row[DIM + c - DH / 2]);
    }
    const float scale = 0.11180339887498949f; // 1/sqrt(80)
    g_q16[idx] = __float2half_rn(fmaf(qv, cv, qr * sv) * scale);
    g_k16[idx] = __float2half_rn(fmaf(kv, cv, kr * sv));
}

// ---------------------------------------------------------------------------
// fp16 tensor-core flash attention. Block = 128 Q rows x (seg, head);
// 8 warps x 16 rows. Double-buffered cp.async K/V; K via ldmatrix,
// V via ldmatrix.trans; P packs locally into A-frags (no shuffles).
// ---------------------------------------------------------------------------
#define KVLD 88                            // K/V smem row stride (halves)
#define KVBUF_BYTES (64 * KVLD * 2)        // 11264
#define ATT_SMEM (4 * KVBUF_BYTES)         // 45056

__global__ __launch_bounds__(256, 2) void attn_f16()
{
    extern __shared__ __half asmem[];
    const uint32_t Ks_base = smem_addr_u32(asmem);
    const uint32_t Vs_base = Ks_base + 2 * KVBUF_BYTES;

    const int tid = threadIdx.x;
    const int lane = tid & 31;
    const int w = tid >> 5;
    const int r = lane >> 2;
    const int cq = lane & 3;

    const int qb = blockIdx.x;
    const int h = blockIdx.y;
    const int seg = blockIdx.z;
    const int qrow = seg * SEGLEN + qb * 128 + w * 16;
    const int hoff = h * DH;

#define AISSUE(kvtv, buf) do {                                               \
    const int _tb = seg * SEGLEN + (kvtv) * 64;                              \
    for (int _c = tid; _c < 640; _c += 256) {                                \
        int _row = _c / 10, _c16 = _c - _row * 10;                           \
        uint32_t _kd = Ks_base + (buf) * KVBUF_BYTES + _row * (KVLD * 2) + _c16 * 16; \
        uint32_t _vd = Vs_base + (buf) * KVBUF_BYTES + _row * (KVLD * 2) + _c16 * 16; \
        const __half* _kp = g_k16 + (size_t)(_tb + _row) * DIM + hoff + _c16 * 8; \
        const __half* _vp = g_qkv16 + (size_t)(_tb + _row) * DIM3 + 2 * DIM + hoff + _c16 * 8; \
        asm volatile(                                                        \
            "cp.async.cg.shared.global [%0], [%1], 16;\n\t"                  \
            "cp.async.cg.shared.global [%2], [%3], 16;\n\t"                  \
            :: "r"(_kd), "l"(_kp), "r"(_vd), "l"(_vp) : "memory");           \
    }                                                                        \
    asm volatile("cp.async.commit_group;" ::: "memory");                     \
} while (0)

    // Q fragments: 5 k-steps of 16 halves
    uint32_t qa[5][4];
    {
        const __half* Qb = g_q16 + (size_t)qrow * DIM + hoff;
#pragma unroll
        for (int ks = 0; ks < 5; ks++) {
            qa[ks][0] = *(const uint32_t*)(Qb + (size_t)r * DIM + ks * 16 + 2 * cq);
            qa[ks][1] = *(const uint32_t*)(Qb + (size_t)(r + 8) * DIM + ks * 16 + 2 * cq);
            qa[ks][2] = *(const uint32_t*)(Qb + (size_t)r * DIM + ks * 16 + 8 + 2 * cq);
            qa[ks][3] = *(const uint32_t*)(Qb + (size_t)(r + 8) * DIM + ks * 16 + 8 + 2 * cq);
        }
    }

    float m0 = -1e30f, m1 = -1e30f, l0 = 0.f, l1 = 0.f;
    float oacc[10][4];
#pragma unroll
    for (int v = 0; v < 10; v++)
#pragma unroll
        for (int c = 0; c < 4; c++) oacc[v][c] = 0.f;

    // ldmatrix lane offsets (bytes within a buffer)
    const uint32_t kb_off = ((uint32_t)((lane & 7) + ((lane >> 4) << 3)) * KVLD +
                            (((lane >> 3) & 1) << 3)) * 2;
    const uint32_t vb_off = ((uint32_t)((lane & 7) + (((lane >> 3) & 1) << 3)) * KVLD +
                            (((lane >> 4) & 1) << 3)) * 2;

    AISSUE(0, 0);

    for (int kvt = 0; kvt < 16; kvt++) {
        const int buf = kvt & 1;
        asm volatile("cp.async.wait_group 0;" ::: "memory");
        __syncthreads();
        if (kvt + 1 < 16) AISSUE(kvt + 1, buf ^ 1);

        const uint32_t kbase = Ks_base + buf * KVBUF_BYTES + kb_off;
        const uint32_t vbase = Vs_base + buf * KVBUF_BYTES + vb_off;

        // S = Q K^T : per k-step, batch 4 LDSM then 8 MMA
        float sc[8][4];
#pragma unroll
        for (int j = 0; j < 8; j++)
#pragma unroll
            for (int c = 0; c < 4; c++) sc[j][c] = 0.f;

#pragma unroll
        for (int ks = 0; ks < 5; ks++) {
            uint32_t bq[4][4];
#pragma unroll
            for (int jp = 0; jp < 4; jp++)
                ldsm_x4(bq[jp], kbase + (uint32_t)(jp * 16 * KVLD * 2) +
                                (uint32_t)(ks * 32));
#pragma unroll
            for (int jp = 0; jp < 4; jp++) {
                mma_f16(sc[jp * 2], qa[ks], &bq[jp][0]);
                mma_f16(sc[jp * 2 + 1], qa[ks], &bq[jp][2]);
            }
        }

        // Online softmax (C-frag layout: rows r / r+8)
        float mx0 = -1e30f, mx1 = -1e30f;
#pragma unroll
        for (int j = 0; j < 8; j++) {
            mx0 = fmaxf(mx0, fmaxf(sc[j][0], sc[j][1]));
            mx1 = fmaxf(mx1, fmaxf(sc[j][2], sc[j][3]));
        }
        mx0 = fmaxf(mx0, __shfl_xor_sync(0xffffffffu, mx0, 1));
        mx0 = fmaxf(mx0, __shfl_xor_sync(0xffffffffu, mx0, 2));
        mx1 = fmaxf(mx1, __shfl_xor_sync(0xffffffffu, mx1, 1));
        mx1 = fmaxf(mx1, __shfl_xor_sync(0xffffffffu, mx1, 2));
        const float nm0 = fmaxf(m0, mx0);
        const float nm1 = fmaxf(m1, mx1);
        const float corr0 = __expf(m0 - nm0);
        const float corr1 = __expf(m1 - nm1);
        m0 = nm0; m1 = nm1;

        float sum0 = 0.f, sum1 = 0.f;
#pragma unroll
        for (int j = 0; j < 8; j++) {
            sc[j][0] = __expf(sc[j][0] - nm0);
            sc[j][1] = __expf(sc[j][1] - nm0);
            sc[j][2] = __expf(sc[j][2] - nm1);
            sc[j][3] = __expf(sc[j][3] - nm1);
            sum0 += sc[j][0] + sc[j][1];
            sum1 += sc[j][2] + sc[j][3];
        }
        sum0 += __shfl_xor_sync(0xffffffffu, sum0, 1);
        sum0 += __shfl_xor_sync(0xffffffffu, sum0, 2);
        sum1 += __shfl_xor_sync(0xffffffffu, sum1, 1);
        sum1 += __shfl_xor_sync(0xffffffffu, sum1, 2);
        l0 = l0 * corr0 + sum0;
        l1 = l1 * corr1 + sum1;

#pragma unroll
        for (int v = 0; v < 10; v++) {
            oacc[v][0] *= corr0; oacc[v][1] *= corr0;
            oacc[v][2] *= corr1; oacc[v][3] *= corr1;
        }

        // O += P V : P packs locally (C-frag -> fp16 A-frag is lane-local)
#pragma unroll
        for (int t = 0; t < 4; t++) {
            uint32_t pa[4];
            pa[0] = pack_h2(sc[2 * t][0], sc[2 * t][1]);
            pa[1] = pack_h2(sc[2 * t][2], sc[2 * t][3]);
            pa[2] = pack_h2(sc[2 * t + 1][0], sc[2 * t + 1][1]);
            pa[3] = pack_h2(sc[2 * t + 1][2], sc[2 * t + 1][3]);
#pragma unroll
            for (int vp = 0; vp < 5; vp++) {
                uint32_t bv[4];
                ldsm_x4_t(bv, vbase + (uint32_t)(t * 16 * KVLD * 2) +
                              (uint32_t)(vp * 32));
                mma_f16(oacc[2 * vp], pa, &bv[0]);
                mma_f16(oacc[2 * vp + 1], pa, &bv[2]);
            }
        }
    }
#undef AISSUE

    // Epilogue: fp16 out (proj GEMM input)
    const float inv0 = 1.f / l0;
    const float inv1 = 1.f / l1;
    __half* O0 = g_attn16 + (size_t)(qrow + r) * DIM + hoff;
    __half* O1 = g_attn16 + (size_t)(qrow + r + 8) * DIM + hoff;
#pragma unroll
    for (int v = 0; v < 10; v++) {
        *(uint32_t*)(O0 + v * 8 + 2 * cq) =
            pack_h2(oacc[v][0] * inv0, oacc[v][1] * inv0);
        *(uint32_t*)(O1 + v * 8 + 2 * cq) =
            pack_h2(oacc[v][2] * inv1, oacc[v][3] * inv1);
    }
}

// ---------------------------------------------------------------------------
extern "C" void kernel_launch(void* const* d_in, const int* in_sizes, int n_in,
                              void* d_out, int out_size)
{
    const float* hs     = (const float*)d_in[0];
    const float* cosp   = (const float*)d_in[1];
    const float* sinp   = (const float*)d_in[2];
    const float* qkv_w  = (const float*)d_in[3];
    const float* qkv_b  = (const float*)d_in[4];
    const float* proj_w = (const float*)d_in[5];
    const float* proj_b = (const float*)d_in[6];
    float* out = (float*)d_out;

    __half *qkv_p, *attn_p, *hs_p, *wq_p, *wp_p;
    cudaGetSymbolAddress((void**)&qkv_p, g_qkv16);
    cudaGetSymbolAddress((void**)&attn_p, g_attn16);
    cudaGetSymbolAddress((void**)&hs_p, g_hs16);
    cudaGetSymbolAddress((void**)&wq_p, g_wq16);
    cudaGetSymbolAddress((void**)&wp_p, g_wp16);

    cudaFuncSetAttribute(gemm_f16_pipe,
                         cudaFuncAttributeMaxDynamicSharedMemorySize, GEMM_SMEM);
    cudaFuncSetAttribute(attn_f16,
                         cudaFuncAttributeMaxDynamicSharedMemorySize, ATT_SMEM);

    // 0) Convert GEMM inputs to fp16
    {
        int n4 = S_TOK * DIM / 4;
        to_f16_kernel<<<(n4 + 255) / 256, 256>>>((const float4*)hs, hs_p, n4);
        n4 = DIM3 * DIM / 4;
        to_f16_kernel<<<(n4 + 255) / 256, 256>>>((const float4*)qkv_w, wq_p, n4);
        n4 = DIM * DIM / 4;
        to_f16_kernel<<<(n4 + 255) / 256, 256>>>((const float4*)proj_w, wp_p, n4);
    }

    // 1) QKV GEMM + bias (fp16 tensor cores), fp16 output
    dim3 g1(DIM3 / 128, S_TOK / 128);
    gemm_f16_pipe<<<g1, 256, GEMM_SMEM>>>(hs_p, wq_p, qkv_b, qkv_p, DIM3, 1);

    // 2) RoPE (folds softmax scale into Q)
    int total = S_TOK * DIM;
    rope16_kernel<<<(total + 255) / 256, 256>>>(cosp, sinp);

    // 3) fp16 tensor-core flash attention
    dim3 g2(SEGLEN / 128, NH, NSEG);
    attn_f16<<<g2, 256, ATT_SMEM>>>();

    // 4) Output projection + bias (fp32 output)
    dim3 g3(DIM / 128, S_TOK / 128);
    gemm_f16_pipe<<<g3, 256, GEMM_SMEM>>>(attn_p, wp_p, proj_b, out, DIM, 0);
}

// round 14
// speedup vs baseline: 1.2162x; 1.0706x over previous
#include <cuda_runtime.h>
#include <cuda_fp16.h>
#include <cstdint>
#include <cstddef>

#define S_TOK 8192
#define DIM 1280
#define DIM3 3840
#define NH 16
#define DH 80
#define NSEG 8
#define SEGLEN 1024
#define GK 1280           // GEMM K (halves)
#define GBK 32            // GEMM k per tile (halves)
#define GNT (GK / GBK)    // 40 k-tiles

// Scratch (device globals: allocation-free per harness rules)
__device__ __half g_qkv16[S_TOK * DIM3];  // qkv result (fp16)
__device__ __half g_q16[S_TOK * DIM];     // roped Q * scale (fp16)
__device__ __half g_k16[S_TOK * DIM];     // roped K (fp16)
__device__ __half g_attn16[S_TOK * DIM];  // attention out (fp16)
__device__ __half g_hs16[S_TOK * DIM];    // fp16 hidden_states
__device__ __half g_wq16[DIM3 * DIM];     // fp16 qkv_w
__device__ __half g_wp16[DIM * DIM];      // fp16 proj_w

// ---------------------------------------------------------------------------
// helpers (baseline PTX, no arch-specific features)
// ---------------------------------------------------------------------------
__device__ __forceinline__ void mma_f16(float* c, const uint32_t* a, const uint32_t* b) {
    asm volatile(
        "mma.sync.aligned.m16n8k16.row.col.f32.f16.f16.f32 "
        "{%0,%1,%2,%3}, {%4,%5,%6,%7}, {%8,%9}, {%0,%1,%2,%3};"
        : "+f"(c[0]), "+f"(c[1]), "+f"(c[2]), "+f"(c[3])
        : "r"(a[0]), "r"(a[1]), "r"(a[2]), "r"(a[3]), "r"(b[0]), "r"(b[1]));
}

__device__ __forceinline__ void ldsm_x4(uint32_t* r, uint32_t addr) {
    asm volatile(
        "ldmatrix.sync.aligned.m8n8.x4.shared.b16 {%0,%1,%2,%3}, [%4];"
        : "=r"(r[0]), "=r"(r[1]), "=r"(r[2]), "=r"(r[3]) : "r"(addr));
}

__device__ __forceinline__ void ldsm_x4_t(uint32_t* r, uint32_t addr) {
    asm volatile(
        "ldmatrix.sync.aligned.m8n8.x4.trans.shared.b16 {%0,%1,%2,%3}, [%4];"
        : "=r"(r[0]), "=r"(r[1]), "=r"(r[2]), "=r"(r[3]) : "r"(addr));
}

__device__ __forceinline__ uint32_t smem_addr_u32(const void* p) {
    return (uint32_t)__cvta_generic_to_shared(p);
}

__device__ __forceinline__ uint32_t pack_h2(float a, float b) {
    __half2 h = __floats2half2_rn(a, b);
    return *(uint32_t*)&h;
}

// ---------------------------------------------------------------------------
// fp32 -> fp16 convert (vectorized)
// ---------------------------------------------------------------------------
__global__ void to_f16_kernel(const float4* __restrict__ src,
                              __half* __restrict__ dst, int n4)
{
    int i = blockIdx.x * blockDim.x + threadIdx.x;
    if (i >= n4) return;
    float4 v = src[i];
    uint2 o;
    o.x = pack_h2(v.x, v.y);
    o.y = pack_h2(v.z, v.w);
    *(uint2*)(dst + (size_t)i * 4) = o;
}

// ---------------------------------------------------------------------------
// fp16 tensor-core GEMM (NT): C[M,N] = A[M,1280] @ B[N,1280]^T + bias[N]
// BM=BN=128, BK=32 halves, 256 threads (8 warps, 2Mx4N, warp tile 64x32).
// 5-stage cp.async pipeline; fragments via ldmatrix, batch-then-compute.
// ---------------------------------------------------------------------------
#define GLDH 40                            // smem row stride in halves
#define STAGES 5
#define STAGE_BYTES (128 * GLDH * 2)       // 10240
#define GEMM_SMEM (STAGES * 2 * STAGE_BYTES)  // 102400

__global__ __launch_bounds__(256, 2) void gemm_f16_pipe(
    const __half* __restrict__ A, const __half* __restrict__ B,
    const float* __restrict__ bias, void* __restrict__ Cout,
    int N, int half_out)
{
    extern __shared__ __half smp[];
    __half* As = smp;                                 // [STAGES][128][GLDH]
    __half* Bs = smp + STAGES * 128 * GLDH;

    const int tid = threadIdx.x;
    const int lane = tid & 31;
    const int wid = tid >> 5;
    const int wm = (wid & 1) * 64;
    const int wn = (wid >> 1) * 32;
    const int bm = blockIdx.y * 128;
    const int bn = blockIdx.x * 128;

    const int lrow = tid >> 1;            // 0..127
    const int lhh = (tid & 1) * 16;       // halves 0 or 16
    const __half* Ag = A + (size_t)(bm + lrow) * GK + lhh;
    const __half* Bg = B + (size_t)(bn + lrow) * GK + lhh;

    const uint32_t As_base = smem_addr_u32(As);
    const uint32_t Bs_base = smem_addr_u32(Bs);
    const uint32_t sA = As_base + (uint32_t)(lrow * GLDH + lhh) * 2;
    const uint32_t sB = Bs_base + (uint32_t)(lrow * GLDH + lhh) * 2;

    // ldmatrix lane offsets (bytes within a stage)
    const uint32_t a_off = ((uint32_t)(wm + (lane & 15)) * GLDH +
                            ((lane >> 4) << 3)) * 2;
    const uint32_t b_off = ((uint32_t)(wn + (lane & 7) + ((lane >> 4) << 3)) * GLDH +
                            (((lane >> 3) & 1) << 3)) * 2;

    float acc[4][4][4];
#pragma unroll
    for (int i = 0; i < 4; i++)
#pragma unroll
        for (int j = 0; j < 4; j++)
#pragma unroll
            for (int c = 0; c < 4; c++) acc[i][j][c] = 0.f;

#define ISSUE(ktv) do {                                                      \
    const int _st = (ktv) % STAGES;                                          \
    const __half* _ap = Ag + (ktv) * GBK;                                    \
    const __half* _bp = Bg + (ktv) * GBK;                                    \
    uint32_t _da = sA + _st * STAGE_BYTES;                                   \
    uint32_t _db = sB + _st * STAGE_BYTES;                                   \
    asm volatile(                                                            \
        "cp.async.cg.shared.global [%0], [%1], 16;\n\t"                      \
        "cp.async.cg.shared.global [%2], [%3], 16;\n\t"                      \
        "cp.async.cg.shared.global [%4], [%5], 16;\n\t"                      \
        "cp.async.cg.shared.global [%6], [%7], 16;\n\t"                      \
        "cp.async.commit_group;"                                             \
        :: "r"(_da), "l"(_ap), "r"(_da + 16), "l"(_ap + 8),                  \
           "r"(_db), "l"(_bp), "r"(_db + 16), "l"(_bp + 8) : "memory");      \
} while (0)

#pragma unroll
    for (int s = 0; s < STAGES - 1; s++) ISSUE(s);

    for (int kt = 0; kt < GNT; ++kt) {
        const int st = kt % STAGES;
        asm volatile("cp.async.wait_group %0;" :: "n"(STAGES - 2));
        __syncthreads();
        if (kt + STAGES - 1 < GNT) ISSUE(kt + STAGES - 1);

        const uint32_t a_base = As_base + st * STAGE_BYTES + a_off;
        const uint32_t b_base = Bs_base + st * STAGE_BYTES + b_off;

        // Batch ALL fragment loads (both k-steps), then all MMAs.
        uint32_t af[2][4][4], bq[2][2][4];
#pragma unroll
        for (int ks = 0; ks < 2; ++ks) {
            const uint32_t kcb = ks * 16 * 2;
#pragma unroll
            for (int i = 0; i < 4; i++)
                ldsm_x4(af[ks][i], a_base + (uint32_t)(i * 16 * GLDH * 2) + kcb);
#pragma unroll
            for (int jp = 0; jp < 2; jp++)
                ldsm_x4(bq[ks][jp], b_base + (uint32_t)(jp * 16 * GLDH * 2) + kcb);
        }
#pragma unroll
        for (int ks = 0; ks < 2; ++ks)
#pragma unroll
            for (int i = 0; i < 4; i++)
#pragma unroll
                for (int j = 0; j < 4; j++)
                    mma_f16(acc[i][j], af[ks][i], &bq[ks][j >> 1][(j & 1) * 2]);
    }
#undef ISSUE

    const int r = lane >> 2;
    const int cq = lane & 3;
#pragma unroll
    for (int i = 0; i < 4; i++) {
        const int row0 = bm + wm + i * 16 + r;
#pragma unroll
        for (int j = 0; j < 4; j++) {
            const int col = bn + wn + j * 8 + cq * 2;
            const float b0 = bias[col], b1 = bias[col + 1];
            if (half_out) {
                __half* C16 = (__half*)Cout;
                *(uint32_t*)(C16 + (size_t)row0 * N + col) =
                    pack_h2(acc[i][j][0] + b0, acc[i][j][1] + b1);
                *(uint32_t*)(C16 + (size_t)(row0 + 8) * N + col) =
                    pack_h2(acc[i][j][2] + b0, acc[i][j][3] + b1);
            } else {
                float* C32 = (float*)Cout;
                float2 v;
                v.x = acc[i][j][0] + b0; v.y = acc[i][j][1] + b1;
                *(float2*)(C32 + (size_t)row0 * N + col) = v;
                v.x = acc[i][j][2] + b0; v.y = acc[i][j][3] + b1;
                *(float2*)(C32 + (size_t)(row0 + 8) * N + col) = v;
            }
        }
    }
}

// ---------------------------------------------------------------------------
// RoPE on fp16 qkv (half2-vectorized): q <- (q*cos + rot(q)*sin)*scale,
// k <- k*cos + rot(k)*sin.  Even-aligned pairs never straddle the d=40
// rotate boundary (40 is even), so both lanes share the sign branch.
// ---------------------------------------------------------------------------
__global__ void rope16_kernel(const float* __restrict__ cosp,
                              const float* __restrict__ sinp)
{
    int idx = blockIdx.x * blockDim.x + threadIdx.x;   // pair index
    if (idx >= S_TOK * (DIM / 2)) return;
    int s = idx / (DIM / 2);
    int c = (idx - s * (DIM / 2)) * 2;
    int d = c % DH;
    float2 cv = *(const float2*)&cosp[s * DH + d];
    float2 sv = *(const float2*)&sinp[s * DH + d];
    const __half* row = g_qkv16 + (size_t)s * DIM3;
    __half2 qh = *(const __half2*)&row[c];
    __half2 kh = *(const __half2*)&row[DIM + c];
    __half2 qrh, krh;
    float sgn;
    if (d < DH / 2) {
        qrh = *(const __half2*)&row[c + DH / 2];
        krh = *(const __half2*)&row[DIM + c + DH / 2];
        sgn = -1.f;
    } else {
        qrh = *(const __half2*)&row[c - DH / 2];
        krh = *(const __half2*)&row[DIM + c - DH / 2];
        sgn = 1.f;
    }
    float2 q = __half22float2(qh), k = __half22float2(kh);
    float2 qr = __half22float2(qrh), kr = __half22float2(krh);
    const float scale = 0.11180339887498949f; // 1/sqrt(80)
    float q0 = fmaf(q.x, cv.x, sgn * qr.x * sv.x) * scale;
    float q1 = fmaf(q.y, cv.y, sgn * qr.y * sv.y) * scale;
    float k0 = fmaf(k.x, cv.x, sgn * kr.x * sv.x);
    float k1 = fmaf(k.y, cv.y, sgn * kr.y * sv.y);
    *(uint32_t*)&g_q16[(size_t)s * DIM + c] = pack_h2(q0, q1);
    *(uint32_t*)&g_k16[(size_t)s * DIM + c] = pack_h2(k0, k1);
}

// ---------------------------------------------------------------------------
// fp16 tensor-core flash attention. Block = 128 Q rows x (seg, head);
// 8 warps x 16 rows. Triple-buffered cp.async K/V (depth-2 prefetch);
// K via ldmatrix, V via ldmatrix.trans; P packs locally (no shuffles).
// ---------------------------------------------------------------------------
#define KVLD 88                            // K/V smem row stride (halves)
#define KVBUF_BYTES (64 * KVLD * 2)        // 11264
#define NBUF 3
#define ATT_SMEM (2 * NBUF * KVBUF_BYTES)  // 67584

__global__ __launch_bounds__(256, 2) void attn_f16()
{
    extern __shared__ __half asmem[];
    const uint32_t Ks_base = smem_addr_u32(asmem);
    const uint32_t Vs_base = Ks_base + NBUF * KVBUF_BYTES;

    const int tid = threadIdx.x;
    const int lane = tid & 31;
    const int w = tid >> 5;
    const int r = lane >> 2;
    const int cq = lane & 3;

    const int qb = blockIdx.x;
    const int h = blockIdx.y;
    const int seg = blockIdx.z;
    const int qrow = seg * SEGLEN + qb * 128 + w * 16;
    const int hoff = h * DH;

#define AISSUE(kvtv, buf) do {                                               \
    const int _tb = seg * SEGLEN + (kvtv) * 64;                              \
    for (int _c = tid; _c < 640; _c += 256) {                                \
        int _row = _c / 10, _c16 = _c - _row * 10;                           \
        uint32_t _kd = Ks_base + (buf) * KVBUF_BYTES + _row * (KVLD * 2) + _c16 * 16; \
        uint32_t _vd = Vs_base + (buf) * KVBUF_BYTES + _row * (KVLD * 2) + _c16 * 16; \
        const __half* _kp = g_k16 + (size_t)(_tb + _row) * DIM + hoff + _c16 * 8; \
        const __half* _vp = g_qkv16 + (size_t)(_tb + _row) * DIM3 + 2 * DIM + hoff + _c16 * 8; \
        asm volatile(                                                        \
            "cp.async.cg.shared.global [%0], [%1], 16;\n\t"                  \
            "cp.async.cg.shared.global [%2], [%3], 16;\n\t"                  \
            :: "r"(_kd), "l"(_kp), "r"(_vd), "l"(_vp) : "memory");           \
    }                                                                        \
    asm volatile("cp.async.commit_group;" ::: "memory");                     \
} while (0)

    // Q fragments: 5 k-steps of 16 halves
    uint32_t qa[5][4];
    {
        const __half* Qb = g_q16 + (size_t)qrow * DIM + hoff;
#pragma unroll
        for (int ks = 0; ks < 5; ks++) {
            qa[ks][0] = *(const uint32_t*)(Qb + (size_t)r * DIM + ks * 16 + 2 * cq);
            qa[ks][1] = *(const uint32_t*)(Qb + (size_t)(r + 8) * DIM + ks * 16 + 2 * cq);
            qa[ks][2] = *(const uint32_t*)(Qb + (size_t)r * DIM + ks * 16 + 8 + 2 * cq);
            qa[ks][3] = *(const uint32_t*)(Qb + (size_t)(r + 8) * DIM + ks * 16 + 8 + 2 * cq);
        }
    }

    float m0 = -1e30f, m1 = -1e30f, l0 = 0.f, l1 = 0.f;
    float oacc[10][4];
#pragma unroll
    for (int v = 0; v < 10; v++)
#pragma unroll
        for (int c = 0; c < 4; c++) oacc[v][c] = 0.f;

    // ldmatrix lane offsets (bytes within a buffer)
    const uint32_t kb_off = ((uint32_t)((lane & 7) + ((lane >> 4) << 3)) * KVLD +
                            (((lane >> 3) & 1) << 3)) * 2;
    const uint32_t vb_off = ((uint32_t)((lane & 7) + (((lane >> 3) & 1) << 3)) * KVLD +
                            (((lane >> 4) & 1) << 3)) * 2;

    AISSUE(0, 0);
    AISSUE(1, 1);

    for (int kvt = 0; kvt < 16; kvt++) {
        const int buf = kvt % NBUF;
        asm volatile("cp.async.wait_group 1;" ::: "memory");
        __syncthreads();
        if (kvt + 2 < 16) AISSUE(kvt + 2, (kvt + 2) % NBUF);

        const uint32_t kbase = Ks_base + buf * KVBUF_BYTES + kb_off;
        const uint32_t vbase = Vs_base + buf * KVBUF_BYTES + vb_off;

        // S = Q K^T : per k-step, batch 4 LDSM then 8 MMA
        float sc[8][4];
#pragma unroll
        for (int j = 0; j < 8; j++)
#pragma unroll
            for (int c = 0; c < 4; c++) sc[j][c] = 0.f;

#pragma unroll
        for (int ks = 0; ks < 5; ks++) {
            uint32_t bq[4][4];
#pragma unroll
            for (int jp = 0; jp < 4; jp++)
                ldsm_x4(bq[jp], kbase + (uint32_t)(jp * 16 * KVLD * 2) +
                                (uint32_t)(ks * 32));
#pragma unroll
            for (int jp = 0; jp < 4; jp++) {
                mma_f16(sc[jp * 2], qa[ks], &bq[jp][0]);
                mma_f16(sc[jp * 2 + 1], qa[ks], &bq[jp][2]);
            }
        }

        // Online softmax (C-frag layout: rows r / r+8)
        float mx0 = -1e30f, mx1 = -1e30f;
#pragma unroll
        for (int j = 0; j < 8; j++) {
            mx0 = fmaxf(mx0, fmaxf(sc[j][0], sc[j][1]));
            mx1 = fmaxf(mx1, fmaxf(sc[j][2], sc[j][3]));
        }
        mx0 = fmaxf(mx0, __shfl_xor_sync(0xffffffffu, mx0, 1));
        mx0 = fmaxf(mx0, __shfl_xor_sync(0xffffffffu, mx0, 2));
        mx1 = fmaxf(mx1, __shfl_xor_sync(0xffffffffu, mx1, 1));
        mx1 = fmaxf(mx1, __shfl_xor_sync(0xffffffffu, mx1, 2));
        const float nm0 = fmaxf(m0, mx0);
        const float nm1 = fmaxf(m1, mx1);
        const float corr0 = __expf(m0 - nm0);
        const float corr1 = __expf(m1 - nm1);
        m0 = nm0; m1 = nm1;

        float sum0 = 0.f, sum1 = 0.f;
#pragma unroll
        for (int j = 0; j < 8; j++) {
            sc[j][0] = __expf(sc[j][0] - nm0);
            sc[j][1] = __expf(sc[j][1] - nm0);
            sc[j][2] = __expf(sc[j][2] - nm1);
            sc[j][3] = __expf(sc[j][3] - nm1);
            sum0 += sc[j][0] + sc[j][1];
            sum1 += sc[j][2] + sc[j][3];
        }
        sum0 += __shfl_xor_sync(0xffffffffu, sum0, 1);
        sum0 += __shfl_xor_sync(0xffffffffu, sum0, 2);
        sum1 += __shfl_xor_sync(0xffffffffu, sum1, 1);
        sum1 += __shfl_xor_sync(0xffffffffu, sum1, 2);
        l0 = l0 * corr0 + sum0;
        l1 = l1 * corr1 + sum1;

#pragma unroll
        for (int v = 0; v < 10; v++) {
            oacc[v][0] *= corr0; oacc[v][1] *= corr0;
            oacc[v][2] *= corr1; oacc[v][3] *= corr1;
        }

        // O += P V : P packs locally (C-frag -> fp16 A-frag is lane-local)
#pragma unroll
        for (int t = 0; t < 4; t++) {
            uint32_t pa[4];
            pa[0] = pack_h2(sc[2 * t][0], sc[2 * t][1]);
            pa[1] = pack_h2(sc[2 * t][2], sc[2 * t][3]);
            pa[2] = pack_h2(sc[2 * t + 1][0], sc[2 * t + 1][1]);
            pa[3] = pack_h2(sc[2 * t + 1][2], sc[2 * t + 1][3]);
#pragma unroll
            for (int vp = 0; vp < 5; vp++) {
                uint32_t bv[4];
                ldsm_x4_t(bv, vbase + (uint32_t)(t * 16 * KVLD * 2) +
                              (uint32_t)(vp * 32));
                mma_f16(oacc[2 * vp], pa, &bv[0]);
                mma_f16(oacc[2 * vp + 1], pa, &bv[2]);
            }
        }
    }
#undef AISSUE

    // Epilogue: fp16 out (proj GEMM input)
    const float inv0 = 1.f / l0;
    const float inv1 = 1.f / l1;
    __half* O0 = g_attn16 + (size_t)(qrow + r) * DIM + hoff;
    __half* O1 = g_attn16 + (size_t)(qrow + r + 8) * DIM + hoff;
#pragma unroll
    for (int v = 0; v < 10; v++) {
        *(uint32_t*)(O0 + v * 8 + 2 * cq) =
            pack_h2(oacc[v][0] * inv0, oacc[v][1] * inv0);
        *(uint32_t*)(O1 + v * 8 + 2 * cq) =
            pack_h2(oacc[v][2] * inv1, oacc[v][3] * inv1);
    }
}

// ---------------------------------------------------------------------------
extern "C" void kernel_launch(void* const* d_in, const int* in_sizes, int n_in,
                              void* d_out, int out_size)
{
    const float* hs     = (const float*)d_in[0];
    const float* cosp   = (const float*)d_in[1];
    const float* sinp   = (const float*)d_in[2];
    const float* qkv_w  = (const float*)d_in[3];
    const float* qkv_b  = (const float*)d_in[4];
    const float* proj_w = (const float*)d_in[5];
    const float* proj_b = (const float*)d_in[6];
    float* out = (float*)d_out;

    __half *qkv_p, *attn_p, *hs_p, *wq_p, *wp_p;
    cudaGetSymbolAddress((void**)&qkv_p, g_qkv16);
    cudaGetSymbolAddress((void**)&attn_p, g_attn16);
    cudaGetSymbolAddress((void**)&hs_p, g_hs16);
    cudaGetSymbolAddress((void**)&wq_p, g_wq16);
    cudaGetSymbolAddress((void**)&wp_p, g_wp16);

    cudaFuncSetAttribute(gemm_f16_pipe,
                         cudaFuncAttributeMaxDynamicSharedMemorySize, GEMM_SMEM);
    cudaFuncSetAttribute(attn_f16,
                         cudaFuncAttributeMaxDynamicSharedMemorySize, ATT_SMEM);

    // 0) Convert GEMM inputs to fp16
    {
        int n4 = S_TOK * DIM / 4;
        to_f16_kernel<<<(n4 + 255) / 256, 256>>>((const float4*)hs, hs_p, n4);
        n4 = DIM3 * DIM / 4;
        to_f16_kernel<<<(n4 + 255) / 256, 256>>>((const float4*)qkv_w, wq_p, n4);
        n4 = DIM * DIM / 4;
        to_f16_kernel<<<(n4 + 255) / 256, 256>>>((const float4*)proj_w, wp_p, n4);
    }

    // 1) QKV GEMM + bias (fp16 tensor cores), fp16 output
    dim3 g1(DIM3 / 128, S_TOK / 128);
    gemm_f16_pipe<<<g1, 256, GEMM_SMEM>>>(hs_p, wq_p, qkv_b, qkv_p, DIM3, 1);

    // 2) RoPE (folds softmax scale into Q), half2-vectorized
    int pairs = S_TOK * (DIM / 2);
    rope16_kernel<<<(pairs + 255) / 256, 256>>>(cosp, sinp);

    // 3) fp16 tensor-core flash attention (triple-buffered)
    dim3 g2(SEGLEN / 128, NH, NSEG);
    attn_f16<<<g2, 256, ATT_SMEM>>>();

    // 4) Output projection + bias (fp32 output)
    dim3 g3(DIM / 128, S_TOK / 128);
    gemm_f16_pipe<<<g3, 256, GEMM_SMEM>>>(attn_p, wp_p, proj_b, out, DIM, 0);
}

// round 15
// speedup vs baseline: 1.2600x; 1.0360x over previous
#include <cuda_runtime.h>
#include <cuda_fp16.h>
#include <cstdint>
#include <cstddef>

#define S_TOK 8192
#define DIM 1280
#define DIM3 3840
#define NH 16
#define DH 80
#define NSEG 8
#define SEGLEN 1024
#define GK 1280           // GEMM K (halves)
#define GBK 32            // GEMM k per tile (halves)
#define GNT (GK / GBK)    // 40 k-tiles

// Scratch (device globals: allocation-free per harness rules)
__device__ __half g_qkv16[S_TOK * DIM3];  // qkv result (fp16)
__device__ __half g_q16[S_TOK * DIM];     // roped Q * scale (fp16)
__device__ __half g_k16[S_TOK * DIM];     // roped K (fp16)
__device__ __half g_attn16[S_TOK * DIM];  // attention out (fp16)
__device__ __half g_hs16[S_TOK * DIM];    // fp16 hidden_states
__device__ __half g_wq16[DIM3 * DIM];     // fp16 qkv_w
__device__ __half g_wp16[DIM * DIM];      // fp16 proj_w

// ---------------------------------------------------------------------------
// helpers (baseline PTX, no arch-specific features)
// ---------------------------------------------------------------------------
__device__ __forceinline__ void mma_f16(float* c, const uint32_t* a, const uint32_t* b) {
    asm volatile(
        "mma.sync.aligned.m16n8k16.row.col.f32.f16.f16.f32 "
        "{%0,%1,%2,%3}, {%4,%5,%6,%7}, {%8,%9}, {%0,%1,%2,%3};"
        : "+f"(c[0]), "+f"(c[1]), "+f"(c[2]), "+f"(c[3])
        : "r"(a[0]), "r"(a[1]), "r"(a[2]), "r"(a[3]), "r"(b[0]), "r"(b[1]));
}

__device__ __forceinline__ void ldsm_x4(uint32_t* r, uint32_t addr) {
    asm volatile(
        "ldmatrix.sync.aligned.m8n8.x4.shared.b16 {%0,%1,%2,%3}, [%4];"
        : "=r"(r[0]), "=r"(r[1]), "=r"(r[2]), "=r"(r[3]) : "r"(addr));
}

__device__ __forceinline__ void ldsm_x4_t(uint32_t* r, uint32_t addr) {
    asm volatile(
        "ldmatrix.sync.aligned.m8n8.x4.trans.shared.b16 {%0,%1,%2,%3}, [%4];"
        : "=r"(r[0]), "=r"(r[1]), "=r"(r[2]), "=r"(r[3]) : "r"(addr));
}

__device__ __forceinline__ uint32_t smem_addr_u32(const void* p) {
    return (uint32_t)__cvta_generic_to_shared(p);
}

__device__ __forceinline__ uint32_t pack_h2(float a, float b) {
    __half2 h = __floats2half2_rn(a, b);
    return *(uint32_t*)&h;
}

// ---------------------------------------------------------------------------
// fp32 -> fp16 convert (vectorized)
// ---------------------------------------------------------------------------
__global__ void to_f16_kernel(const float4* __restrict__ src,
                              __half* __restrict__ dst, int n4)
{
    int i = blockIdx.x * blockDim.x + threadIdx.x;
    if (i >= n4) return;
    float4 v = src[i];
    uint2 o;
    o.x = pack_h2(v.x, v.y);
    o.y = pack_h2(v.z, v.w);
    *(uint2*)(dst + (size_t)i * 4) = o;
}

// ---------------------------------------------------------------------------
// fp16 tensor-core GEMM (NT): C[M,N] = A[M,1280] @ B[N,1280]^T + bias[N]
// BM=BN=128, BK=32 halves, 256 threads (8 warps, 2Mx4N, warp tile 64x32).
// 4-stage cp.async pipeline; fragments via ldmatrix, batch-then-compute.
// (exact R11 configuration — benched best at QKV=276us)
// ---------------------------------------------------------------------------
#define GLDH 40                            // smem row stride in halves
#define STAGES 4
#define STAGE_BYTES (128 * GLDH * 2)       // 10240
#define GEMM_SMEM (STAGES * 2 * STAGE_BYTES)  // 81920

__global__ __launch_bounds__(256, 2) void gemm_f16_pipe(
    const __half* __restrict__ A, const __half* __restrict__ B,
    const float* __restrict__ bias, void* __restrict__ Cout,
    int N, int half_out)
{
    extern __shared__ __half smp[];
    __half* As = smp;                                 // [STAGES][128][GLDH]
    __half* Bs = smp + STAGES * 128 * GLDH;

    const int tid = threadIdx.x;
    const int lane = tid & 31;
    const int wid = tid >> 5;
    const int wm = (wid & 1) * 64;
    const int wn = (wid >> 1) * 32;
    const int bm = blockIdx.y * 128;
    const int bn = blockIdx.x * 128;

    const int lrow = tid >> 1;            // 0..127
    const int lhh = (tid & 1) * 16;       // halves 0 or 16
    const __half* Ag = A + (size_t)(bm + lrow) * GK + lhh;
    const __half* Bg = B + (size_t)(bn + lrow) * GK + lhh;

    const uint32_t As_base = smem_addr_u32(As);
    const uint32_t Bs_base = smem_addr_u32(Bs);
    const uint32_t sA = As_base + (uint32_t)(lrow * GLDH + lhh) * 2;
    const uint32_t sB = Bs_base + (uint32_t)(lrow * GLDH + lhh) * 2;

    // ldmatrix lane offsets (bytes within a stage)
    const uint32_t a_off = ((uint32_t)(wm + (lane & 15)) * GLDH +
                            ((lane >> 4) << 3)) * 2;
    const uint32_t b_off = ((uint32_t)(wn + (lane & 7) + ((lane >> 4) << 3)) * GLDH +
                            (((lane >> 3) & 1) << 3)) * 2;

    float acc[4][4][4];
#pragma unroll
    for (int i = 0; i < 4; i++)
#pragma unroll
        for (int j = 0; j < 4; j++)
#pragma unroll
            for (int c = 0; c < 4; c++) acc[i][j][c] = 0.f;

#define ISSUE(ktv) do {                                                      \
    const int _st = (ktv) % STAGES;                                          \
    const __half* _ap = Ag + (ktv) * GBK;                                    \
    const __half* _bp = Bg + (ktv) * GBK;                                    \
    uint32_t _da = sA + _st * STAGE_BYTES;                                   \
    uint32_t _db = sB + _st * STAGE_BYTES;                                   \
    asm volatile(                                                            \
        "cp.async.cg.shared.global [%0], [%1], 16;\n\t"                      \
        "cp.async.cg.shared.global [%2], [%3], 16;\n\t"                      \
        "cp.async.cg.shared.global [%4], [%5], 16;\n\t"                      \
        "cp.async.cg.shared.global [%6], [%7], 16;\n\t"                      \
        "cp.async.commit_group;"                                             \
        :: "r"(_da), "l"(_ap), "r"(_da + 16), "l"(_ap + 8),                  \
           "r"(_db), "l"(_bp), "r"(_db + 16), "l"(_bp + 8) : "memory");      \
} while (0)

#pragma unroll
    for (int s = 0; s < STAGES - 1; s++) ISSUE(s);

    for (int kt = 0; kt < GNT; ++kt) {
        const int st = kt % STAGES;
        asm volatile("cp.async.wait_group %0;" :: "n"(STAGES - 2));
        __syncthreads();
        if (kt + STAGES - 1 < GNT) ISSUE(kt + STAGES - 1);

        const uint32_t a_base = As_base + st * STAGE_BYTES + a_off;
        const uint32_t b_base = Bs_base + st * STAGE_BYTES + b_off;

        // Batch ALL fragment loads (both k-steps), then all MMAs.
        uint32_t af[2][4][4], bq[2][2][4];
#pragma unroll
        for (int ks = 0; ks < 2; ++ks) {
            const uint32_t kcb = ks * 16 * 2;
#pragma unroll
            for (int i = 0; i < 4; i++)
                ldsm_x4(af[ks][i], a_base + (uint32_t)(i * 16 * GLDH * 2) + kcb);
#pragma unroll
            for (int jp = 0; jp < 2; jp++)
                ldsm_x4(bq[ks][jp], b_base + (uint32_t)(jp * 16 * GLDH * 2) + kcb);
        }
#pragma unroll
        for (int ks = 0; ks < 2; ++ks)
#pragma unroll
            for (int i = 0; i < 4; i++)
#pragma unroll
                for (int j = 0; j < 4; j++)
                    mma_f16(acc[i][j], af[ks][i], &bq[ks][j >> 1][(j & 1) * 2]);
    }
#undef ISSUE

    const int r = lane >> 2;
    const int cq = lane & 3;
#pragma unroll
    for (int i = 0; i < 4; i++) {
        const int row0 = bm + wm + i * 16 + r;
#pragma unroll
        for (int j = 0; j < 4; j++) {
            const int col = bn + wn + j * 8 + cq * 2;
            const float b0 = bias[col], b1 = bias[col + 1];
            if (half_out) {
                __half* C16 = (__half*)Cout;
                *(uint32_t*)(C16 + (size_t)row0 * N + col) =
                    pack_h2(acc[i][j][0] + b0, acc[i][j][1] + b1);
                *(uint32_t*)(C16 + (size_t)(row0 + 8) * N + col) =
                    pack_h2(acc[i][j][2] + b0, acc[i][j][3] + b1);
            } else {
                float* C32 = (float*)Cout;
                float2 v;
                v.x = acc[i][j][0] + b0; v.y = acc[i][j][1] + b1;
                *(float2*)(C32 + (size_t)row0 * N + col) = v;
                v.x = acc[i][j][2] + b0; v.y = acc[i][j][3] + b1;
                *(float2*)(C32 + (size_t)(row0 + 8) * N + col) = v;
            }
        }
    }
}

// ---------------------------------------------------------------------------
// RoPE on fp16 qkv (half2-vectorized): q <- (q*cos + rot(q)*sin)*scale,
// k <- k*cos + rot(k)*sin.  Even-aligned pairs never straddle the d=40
// rotate boundary (40 is even), so both lanes share the sign branch.
// ---------------------------------------------------------------------------
__global__ void rope16_kernel(const float* __restrict__ cosp,
                              const float* __restrict__ sinp)
{
    int idx = blockIdx.x * blockDim.x + threadIdx.x;   // pair index
    if (idx >= S_TOK * (DIM / 2)) return;
    int s = idx / (DIM / 2);
    int c = (idx - s * (DIM / 2)) * 2;
    int d = c % DH;
    float2 cv = *(const float2*)&cosp[s * DH + d];
    float2 sv = *(const float2*)&sinp[s * DH + d];
    const __half* row = g_qkv16 + (size_t)s * DIM3;
    __half2 qh = *(const __half2*)&row[c];
    __half2 kh = *(const __half2*)&row[DIM + c];
    __half2 qrh, krh;
    float sgn;
    if (d < DH / 2) {
        qrh = *(const __half2*)&row[c + DH / 2];
        krh = *(const __half2*)&row[DIM + c + DH / 2];
        sgn = -1.f;
    } else {
        qrh = *(const __half2*)&row[c - DH / 2];
        krh = *(const __half2*)&row[DIM + c - DH / 2];
        sgn = 1.f;
    }
    float2 q = __half22float2(qh), k = __half22float2(kh);
    float2 qr = __half22float2(qrh), kr = __half22float2(krh);
    const float scale = 0.11180339887498949f; // 1/sqrt(80)
    float q0 = fmaf(q.x, cv.x, sgn * qr.x * sv.x) * scale;
    float q1 = fmaf(q.y, cv.y, sgn * qr.y * sv.y) * scale;
    float k0 = fmaf(k.x, cv.x, sgn * kr.x * sv.x);
    float k1 = fmaf(k.y, cv.y, sgn * kr.y * sv.y);
    *(uint32_t*)&g_q16[(size_t)s * DIM + c] = pack_h2(q0, q1);
    *(uint32_t*)&g_k16[(size_t)s * DIM + c] = pack_h2(k0, k1);
}

// ---------------------------------------------------------------------------
// fp16 tensor-core flash attention. Block = 128 Q rows x (seg, head);
// 8 warps x 16 rows. Triple-buffered cp.async K/V (depth-2 prefetch);
// K via ldmatrix, V via ldmatrix.trans; P packs locally (no shuffles).
// ---------------------------------------------------------------------------
#define KVLD 88                            // K/V smem row stride (halves)
#define KVBUF_BYTES (64 * KVLD * 2)        // 11264
#define NBUF 3
#define ATT_SMEM (2 * NBUF * KVBUF_BYTES)  // 67584

__global__ __launch_bounds__(256, 2) void attn_f16()
{
    extern __shared__ __half asmem[];
    const uint32_t Ks_base = smem_addr_u32(asmem);
    const uint32_t Vs_base = Ks_base + NBUF * KVBUF_BYTES;

    const int tid = threadIdx.x;
    const int lane = tid & 31;
    const int w = tid >> 5;
    const int r = lane >> 2;
    const int cq = lane & 3;

    const int qb = blockIdx.x;
    const int h = blockIdx.y;
    const int seg = blockIdx.z;
    const int qrow = seg * SEGLEN + qb * 128 + w * 16;
    const int hoff = h * DH;

#define AISSUE(kvtv, buf) do {                                               \
    const int _tb = seg * SEGLEN + (kvtv) * 64;                              \
    for (int _c = tid; _c < 640; _c += 256) {                                \
        int _row = _c / 10, _c16 = _c - _row * 10;                           \
        uint32_t _kd = Ks_base + (buf) * KVBUF_BYTES + _row * (KVLD * 2) + _c16 * 16; \
        uint32_t _vd = Vs_base + (buf) * KVBUF_BYTES + _row * (KVLD * 2) + _c16 * 16; \
        const __half* _kp = g_k16 + (size_t)(_tb + _row) * DIM + hoff + _c16 * 8; \
        const __half* _vp = g_qkv16 + (size_t)(_tb + _row) * DIM3 + 2 * DIM + hoff + _c16 * 8; \
        asm volatile(                                                        \
            "cp.async.cg.shared.global [%0], [%1], 16;\n\t"                  \
            "cp.async.cg.shared.global [%2], [%3], 16;\n\t"                  \
            :: "r"(_kd), "l"(_kp), "r"(_vd), "l"(_vp) : "memory");           \
    }                                                                        \
    asm volatile("cp.async.commit_group;" ::: "memory");                     \
} while (0)

    // Q fragments: 5 k-steps of 16 halves
    uint32_t qa[5][4];
    {
        const __half* Qb = g_q16 + (size_t)qrow * DIM + hoff;
#pragma unroll
        for (int ks = 0; ks < 5; ks++) {
            qa[ks][0] = *(const uint32_t*)(Qb + (size_t)r * DIM + ks * 16 + 2 * cq);
            qa[ks][1] = *(const uint32_t*)(Qb + (size_t)(r + 8) * DIM + ks * 16 + 2 * cq);
            qa[ks][2] = *(const uint32_t*)(Qb + (size_t)r * DIM + ks * 16 + 8 + 2 * cq);
            qa[ks][3] = *(const uint32_t*)(Qb + (size_t)(r + 8) * DIM + ks * 16 + 8 + 2 * cq);
        }
    }

    float m0 = -1e30f, m1 = -1e30f, l0 = 0.f, l1 = 0.f;
    float oacc[10][4];
#pragma unroll
    for (int v = 0; v < 10; v++)
#pragma unroll
        for (int c = 0; c < 4; c++) oacc[v][c] = 0.f;

    // ldmatrix lane offsets (bytes within a buffer)
    const uint32_t kb_off = ((uint32_t)((lane & 7) + ((lane >> 4) << 3)) * KVLD +
                            (((lane >> 3) & 1) << 3)) * 2;
    const uint32_t vb_off = ((uint32_t)((lane & 7) + (((lane >> 3) & 1) << 3)) * KVLD +
                            (((lane >> 4) & 1) << 3)) * 2;

    AISSUE(0, 0);
    AISSUE(1, 1);

    for (int kvt = 0; kvt < 16; kvt++) {
        const int buf = kvt % NBUF;
        asm volatile("cp.async.wait_group 1;" ::: "memory");
        __syncthreads();
        if (kvt + 2 < 16) AISSUE(kvt + 2, (kvt + 2) % NBUF);

        const uint32_t kbase = Ks_base + buf * KVBUF_BYTES + kb_off;
        const uint32_t vbase = Vs_base + buf * KVBUF_BYTES + vb_off;

        // S = Q K^T : per k-step, batch 4 LDSM then 8 MMA
        float sc[8][4];
#pragma unroll
        for (int j = 0; j < 8; j++)
#pragma unroll
            for (int c = 0; c < 4; c++) sc[j][c] = 0.f;

#pragma unroll
        for (int ks = 0; ks < 5; ks++) {
            uint32_t bq[4][4];
#pragma unroll
            for (int jp = 0; jp < 4; jp++)
                ldsm_x4(bq[jp], kbase + (uint32_t)(jp * 16 * KVLD * 2) +
                                (uint32_t)(ks * 32));
#pragma unroll
            for (int jp = 0; jp < 4; jp++) {
                mma_f16(sc[jp * 2], qa[ks], &bq[jp][0]);
                mma_f16(sc[jp * 2 + 1], qa[ks], &bq[jp][2]);
            }
        }

        // Online softmax (C-frag layout: rows r / r+8)
        float mx0 = -1e30f, mx1 = -1e30f;
#pragma unroll
        for (int j = 0; j < 8; j++) {
            mx0 = fmaxf(mx0, fmaxf(sc[j][0], sc[j][1]));
            mx1 = fmaxf(mx1, fmaxf(sc[j][2], sc[j][3]));
        }
        mx0 = fmaxf(mx0, __shfl_xor_sync(0xffffffffu, mx0, 1));
        mx0 = fmaxf(mx0, __shfl_xor_sync(0xffffffffu, mx0, 2));
        mx1 = fmaxf(mx1, __shfl_xor_sync(0xffffffffu, mx1, 1));
        mx1 = fmaxf(mx1, __shfl_xor_sync(0xffffffffu, mx1, 2));
        const float nm0 = fmaxf(m0, mx0);
        const float nm1 = fmaxf(m1, mx1);
        const float corr0 = __expf(m0 - nm0);
        const float corr1 = __expf(m1 - nm1);
        m0 = nm0; m1 = nm1;

        float sum0 = 0.f, sum1 = 0.f;
#pragma unroll
        for (int j = 0; j < 8; j++) {
            sc[j][0] = __expf(sc[j][0] - nm0);
            sc[j][1] = __expf(sc[j][1] - nm0);
            sc[j][2] = __expf(sc[j][2] - nm1);
            sc[j][3] = __expf(sc[j][3] - nm1);
            sum0 += sc[j][0] + sc[j][1];
            sum1 += sc[j][2] + sc[j][3];
        }
        sum0 += __shfl_xor_sync(0xffffffffu, sum0, 1);
        sum0 += __shfl_xor_sync(0xffffffffu, sum0, 2);
        sum1 += __shfl_xor_sync(0xffffffffu, sum1, 1);
        sum1 += __shfl_xor_sync(0xffffffffu, sum1, 2);
        l0 = l0 * corr0 + sum0;
        l1 = l1 * corr1 + sum1;

#pragma unroll
        for (int v = 0; v < 10; v++) {
            oacc[v][0] *= corr0; oacc[v][1] *= corr0;
            oacc[v][2] *= corr1; oacc[v][3] *= corr1;
        }

        // O += P V : P packs locally (C-frag -> fp16 A-frag is lane-local)
#pragma unroll
        for (int t = 0; t < 4; t++) {
            uint32_t pa[4];
            pa[0] = pack_h2(sc[2 * t][0], sc[2 * t][1]);
            pa[1] = pack_h2(sc[2 * t][2], sc[2 * t][3]);
            pa[2] = pack_h2(sc[2 * t + 1][0], sc[2 * t + 1][1]);
            pa[3] = pack_h2(sc[2 * t + 1][2], sc[2 * t + 1][3]);
#pragma unroll
            for (int vp = 0; vp < 5; vp++) {
                uint32_t bv[4];
                ldsm_x4_t(bv, vbase + (uint32_t)(t * 16 * KVLD * 2) +
                              (uint32_t)(vp * 32));
                mma_f16(oacc[2 * vp], pa, &bv[0]);
                mma_f16(oacc[2 * vp + 1], pa, &bv[2]);
            }
        }
    }
#undef AISSUE

    // Epilogue: fp16 out (proj GEMM input)
    const float inv0 = 1.f / l0;
    const float inv1 = 1.f / l1;
    __half* O0 = g_attn16 + (size_t)(qrow + r) * DIM + hoff;
    __half* O1 = g_attn16 + (size_t)(qrow + r + 8) * DIM + hoff;
#pragma unroll
    for (int v = 0; v < 10; v++) {
        *(uint32_t*)(O0 + v * 8 + 2 * cq) =
            pack_h2(oacc[v][0] * inv0, oacc[v][1] * inv0);
        *(uint32_t*)(O1 + v * 8 + 2 * cq) =
            pack_h2(oacc[v][2] * inv1, oacc[v][3] * inv1);
    }
}

// ---------------------------------------------------------------------------
extern "C" void kernel_launch(void* const* d_in, const int* in_sizes, int n_in,
                              void* d_out, int out_size)
{
    const float* hs     = (const float*)d_in[0];
    const float* cosp   = (const float*)d_in[1];
    const float* sinp   = (const float*)d_in[2];
    const float* qkv_w  = (const float*)d_in[3];
    const float* qkv_b  = (const float*)d_in[4];
    const float* proj_w = (const float*)d_in[5];
    const float* proj_b = (const float*)d_in[6];
    float* out = (float*)d_out;

    __half *qkv_p, *attn_p, *hs_p, *wq_p, *wp_p;
    cudaGetSymbolAddress((void**)&qkv_p, g_qkv16);
    cudaGetSymbolAddress((void**)&attn_p, g_attn16);
    cudaGetSymbolAddress((void**)&hs_p, g_hs16);
    cudaGetSymbolAddress((void**)&wq_p, g_wq16);
    cudaGetSymbolAddress((void**)&wp_p, g_wp16);

    cudaFuncSetAttribute(gemm_f16_pipe,
                         cudaFuncAttributeMaxDynamicSharedMemorySize, GEMM_SMEM);
    cudaFuncSetAttribute(attn_f16,
                         cudaFuncAttributeMaxDynamicSharedMemorySize, ATT_SMEM);

    // 0) Convert GEMM inputs to fp16
    {
        int n4 = S_TOK * DIM / 4;
        to_f16_kernel<<<(n4 + 255) / 256, 256>>>((const float4*)hs, hs_p, n4);
        n4 = DIM3 * DIM / 4;
        to_f16_kernel<<<(n4 + 255) / 256, 256>>>((const float4*)qkv_w, wq_p, n4);
        n4 = DIM * DIM / 4;
        to_f16_kernel<<<(n4 + 255) / 256, 256>>>((const float4*)proj_w, wp_p, n4);
    }

    // 1) QKV GEMM + bias (fp16 tensor cores), fp16 output
    dim3 g1(DIM3 / 128, S_TOK / 128);
    gemm_f16_pipe<<<g1, 256, GEMM_SMEM>>>(hs_p, wq_p, qkv_b, qkv_p, DIM3, 1);

    // 2) RoPE (folds softmax scale into Q), half2-vectorized
    int pairs = S_TOK * (DIM / 2);
    rope16_kernel<<<(pairs + 255) / 256, 256>>>(cosp, sinp);

    // 3) fp16 tensor-core flash attention (triple-buffered)
    dim3 g2(SEGLEN / 128, NH, NSEG);
    attn_f16<<<g2, 256, ATT_SMEM>>>();

    // 4) Output projection + bias (fp32 output)
    dim3 g3(DIM / 128, S_TOK / 128);
    gemm_f16_pipe<<<g3, 256, GEMM_SMEM>>>(attn_p, wp_p, proj_b, out, DIM, 0);
}

// round 16
// speedup vs baseline: 1.2663x; 1.0051x over previous
#include <cuda_runtime.h>
#include <cuda_fp16.h>
#include <cstdint>
#include <cstddef>

#define S_TOK 8192
#define DIM 1280
#define DIM3 3840
#define NH 16
#define DH 80
#define NSEG 8
#define SEGLEN 1024
#define GK 1280           // GEMM K (halves)
#define GBK 32            // GEMM k per tile (halves)
#define GNT (GK / GBK)    // 40 k-tiles

// Scratch (device globals: allocation-free per harness rules)
__device__ __half g_qkv16[S_TOK * DIM3];  // qkv result (fp16)
__device__ __half g_q16[S_TOK * DIM];     // roped Q * scale*log2e (fp16)
__device__ __half g_k16[S_TOK * DIM];     // roped K (fp16)
__device__ __half g_attn16[S_TOK * DIM];  // attention out (fp16)
__device__ __half g_hs16[S_TOK * DIM];    // fp16 hidden_states
__device__ __half g_wq16[DIM3 * DIM];     // fp16 qkv_w
__device__ __half g_wp16[DIM * DIM];      // fp16 proj_w

// ---------------------------------------------------------------------------
// helpers (baseline PTX, no arch-specific features)
// ---------------------------------------------------------------------------
__device__ __forceinline__ void mma_f16(float* c, const uint32_t* a, const uint32_t* b) {
    asm volatile(
        "mma.sync.aligned.m16n8k16.row.col.f32.f16.f16.f32 "
        "{%0,%1,%2,%3}, {%4,%5,%6,%7}, {%8,%9}, {%0,%1,%2,%3};"
        : "+f"(c[0]), "+f"(c[1]), "+f"(c[2]), "+f"(c[3])
        : "r"(a[0]), "r"(a[1]), "r"(a[2]), "r"(a[3]), "r"(b[0]), "r"(b[1]));
}

__device__ __forceinline__ void ldsm_x4(uint32_t* r, uint32_t addr) {
    asm volatile(
        "ldmatrix.sync.aligned.m8n8.x4.shared.b16 {%0,%1,%2,%3}, [%4];"
        : "=r"(r[0]), "=r"(r[1]), "=r"(r[2]), "=r"(r[3]) : "r"(addr));
}

__device__ __forceinline__ void ldsm_x4_t(uint32_t* r, uint32_t addr) {
    asm volatile(
        "ldmatrix.sync.aligned.m8n8.x4.trans.shared.b16 {%0,%1,%2,%3}, [%4];"
        : "=r"(r[0]), "=r"(r[1]), "=r"(r[2]), "=r"(r[3]) : "r"(addr));
}

__device__ __forceinline__ uint32_t smem_addr_u32(const void* p) {
    return (uint32_t)__cvta_generic_to_shared(p);
}

__device__ __forceinline__ uint32_t pack_h2(float a, float b) {
    __half2 h = __floats2half2_rn(a, b);
    return *(uint32_t*)&h;
}

// ---------------------------------------------------------------------------
// Merged fp32 -> fp16 convert for hs, qkv_w, proj_w (one launch)
// ---------------------------------------------------------------------------
#define N4_HS   (S_TOK * DIM / 4)
#define N4_WQ   (DIM3 * DIM / 4)
#define N4_WP   (DIM * DIM / 4)
#define N4_ALL  (N4_HS + N4_WQ + N4_WP)

__global__ void convert_all_kernel(const float4* __restrict__ hs,
                                   const float4* __restrict__ wq,
                                   const float4* __restrict__ wp,
                                   __half* __restrict__ hs16,
                                   __half* __restrict__ wq16,
                                   __half* __restrict__ wp16)
{
    int i = blockIdx.x * blockDim.x + threadIdx.x;
    if (i >= N4_ALL) return;
    const float4* src;
    __half* dst;
    int k;
    if (i < N4_HS) {
        src = hs; dst = hs16; k = i;
    } else if (i < N4_HS + N4_WQ) {
        src = wq; dst = wq16; k = i - N4_HS;
    } else {
        src = wp; dst = wp16; k = i - N4_HS - N4_WQ;
    }
    float4 v = src[k];
    uint2 o;
    o.x = pack_h2(v.x, v.y);
    o.y = pack_h2(v.z, v.w);
    *(uint2*)(dst + (size_t)k * 4) = o;
}

// ---------------------------------------------------------------------------
// fp16 tensor-core GEMM (NT): C[M,N] = A[M,1280] @ B[N,1280]^T + bias[N]
// BM=BN=128, BK=32 halves, 256 threads (8 warps, 2Mx4N, warp tile 64x32).
// 4-stage cp.async pipeline; fragments via ldmatrix, batch-then-compute.
// (exact R11/R15 configuration — benched best)
// ---------------------------------------------------------------------------
#define GLDH 40                            // smem row stride in halves
#define STAGES 4
#define STAGE_BYTES (128 * GLDH * 2)       // 10240
#define GEMM_SMEM (STAGES * 2 * STAGE_BYTES)  // 81920

__global__ __launch_bounds__(256, 2) void gemm_f16_pipe(
    const __half* __restrict__ A, const __half* __restrict__ B,
    const float* __restrict__ bias, void* __restrict__ Cout,
    int N, int half_out)
{
    extern __shared__ __half smp[];
    __half* As = smp;                                 // [STAGES][128][GLDH]
    __half* Bs = smp + STAGES * 128 * GLDH;

    const int tid = threadIdx.x;
    const int lane = tid & 31;
    const int wid = tid >> 5;
    const int wm = (wid & 1) * 64;
    const int wn = (wid >> 1) * 32;
    const int bm = blockIdx.y * 128;
    const int bn = blockIdx.x * 128;

    const int lrow = tid >> 1;            // 0..127
    const int lhh = (tid & 1) * 16;       // halves 0 or 16
    const __half* Ag = A + (size_t)(bm + lrow) * GK + lhh;
    const __half* Bg = B + (size_t)(bn + lrow) * GK + lhh;

    const uint32_t As_base = smem_addr_u32(As);
    const uint32_t Bs_base = smem_addr_u32(Bs);
    const uint32_t sA = As_base + (uint32_t)(lrow * GLDH + lhh) * 2;
    const uint32_t sB = Bs_base + (uint32_t)(lrow * GLDH + lhh) * 2;

    // ldmatrix lane offsets (bytes within a stage)
    const uint32_t a_off = ((uint32_t)(wm + (lane & 15)) * GLDH +
                            ((lane >> 4) << 3)) * 2;
    const uint32_t b_off = ((uint32_t)(wn + (lane & 7) + ((lane >> 4) << 3)) * GLDH +
                            (((lane >> 3) & 1) << 3)) * 2;

    float acc[4][4][4];
#pragma unroll
    for (int i = 0; i < 4; i++)
#pragma unroll
        for (int j = 0; j < 4; j++)
#pragma unroll
            for (int c = 0; c < 4; c++) acc[i][j][c] = 0.f;

#define ISSUE(ktv) do {                                                      \
    const int _st = (ktv) % STAGES;                                          \
    const __half* _ap = Ag + (ktv) * GBK;                                    \
    const __half* _bp = Bg + (ktv) * GBK;                                    \
    uint32_t _da = sA + _st * STAGE_BYTES;                                   \
    uint32_t _db = sB + _st * STAGE_BYTES;                                   \
    asm volatile(                                                            \
        "cp.async.cg.shared.global [%0], [%1], 16;\n\t"                      \
        "cp.async.cg.shared.global [%2], [%3], 16;\n\t"                      \
        "cp.async.cg.shared.global [%4], [%5], 16;\n\t"                      \
        "cp.async.cg.shared.global [%6], [%7], 16;\n\t"                      \
        "cp.async.commit_group;"                                             \
        :: "r"(_da), "l"(_ap), "r"(_da + 16), "l"(_ap + 8),                  \
           "r"(_db), "l"(_bp), "r"(_db + 16), "l"(_bp + 8) : "memory");      \
} while (0)

#pragma unroll
    for (int s = 0; s < STAGES - 1; s++) ISSUE(s);

    for (int kt = 0; kt < GNT; ++kt) {
        const int st = kt % STAGES;
        asm volatile("cp.async.wait_group %0;" :: "n"(STAGES - 2));
        __syncthreads();
        if (kt + STAGES - 1 < GNT) ISSUE(kt + STAGES - 1);

        const uint32_t a_base = As_base + st * STAGE_BYTES + a_off;
        const uint32_t b_base = Bs_base + st * STAGE_BYTES + b_off;

        // Batch ALL fragment loads (both k-steps), then all MMAs.
        uint32_t af[2][4][4], bq[2][2][4];
#pragma unroll
        for (int ks = 0; ks < 2; ++ks) {
            const uint32_t kcb = ks * 16 * 2;
#pragma unroll
            for (int i = 0; i < 4; i++)
                ldsm_x4(af[ks][i], a_base + (uint32_t)(i * 16 * GLDH * 2) + kcb);
#pragma unroll
            for (int jp = 0; jp < 2; jp++)
                ldsm_x4(bq[ks][jp], b_base + (uint32_t)(jp * 16 * GLDH * 2) + kcb);
        }
#pragma unroll
        for (int ks = 0; ks < 2; ++ks)
#pragma unroll
            for (int i = 0; i < 4; i++)
#pragma unroll
                for (int j = 0; j < 4; j++)
                    mma_f16(acc[i][j], af[ks][i], &bq[ks][j >> 1][(j & 1) * 2]);
    }
#undef ISSUE

    const int r = lane >> 2;
    const int cq = lane & 3;
#pragma unroll
    for (int i = 0; i < 4; i++) {
        const int row0 = bm + wm + i * 16 + r;
#pragma unroll
        for (int j = 0; j < 4; j++) {
            const int col = bn + wn + j * 8 + cq * 2;
            const float b0 = bias[col], b1 = bias[col + 1];
            if (half_out) {
                __half* C16 = (__half*)Cout;
                *(uint32_t*)(C16 + (size_t)row0 * N + col) =
                    pack_h2(acc[i][j][0] + b0, acc[i][j][1] + b1);
                *(uint32_t*)(C16 + (size_t)(row0 + 8) * N + col) =
                    pack_h2(acc[i][j][2] + b0, acc[i][j][3] + b1);
            } else {
                float* C32 = (float*)Cout;
                float2 v;
                v.x = acc[i][j][0] + b0; v.y = acc[i][j][1] + b1;
                *(float2*)(C32 + (size_t)row0 * N + col) = v;
                v.x = acc[i][j][2] + b0; v.y = acc[i][j][3] + b1;
                *(float2*)(C32 + (size_t)(row0 + 8) * N + col) = v;
            }
        }
    }
}

// ---------------------------------------------------------------------------
// RoPE on fp16 qkv (half2-vectorized): q <- (q*cos + rot(q)*sin)*scale*log2e,
// k <- k*cos + rot(k)*sin.  log2e folded into Q so attention can use exp2.
// ---------------------------------------------------------------------------
__global__ void rope16_kernel(const float* __restrict__ cosp,
                              const float* __restrict__ sinp)
{
    int idx = blockIdx.x * blockDim.x + threadIdx.x;   // pair index
    if (idx >= S_TOK * (DIM / 2)) return;
    int s = idx / (DIM / 2);
    int c = (idx - s * (DIM / 2)) * 2;
    int d = c % DH;
    float2 cv = *(const float2*)&cosp[s * DH + d];
    float2 sv = *(const float2*)&sinp[s * DH + d];
    const __half* row = g_qkv16 + (size_t)s * DIM3;
    __half2 qh = *(const __half2*)&row[c];
    __half2 kh = *(const __half2*)&row[DIM + c];
    __half2 qrh, krh;
    float sgn;
    if (d < DH / 2) {
        qrh = *(const __half2*)&row[c + DH / 2];
        krh = *(const __half2*)&row[DIM + c + DH / 2];
        sgn = -1.f;
    } else {
        qrh = *(const __half2*)&row[c - DH / 2];
        krh = *(const __half2*)&row[DIM + c - DH / 2];
        sgn = 1.f;
    }
    float2 q = __half22float2(qh), k = __half22float2(kh);
    float2 qr = __half22float2(qrh), kr = __half22float2(krh);
    // 1/sqrt(80) * log2(e)  (exp2-domain softmax)
    const float scale = 0.11180339887498949f * 1.4426950408889634f;
    float q0 = fmaf(q.x, cv.x, sgn * qr.x * sv.x) * scale;
    float q1 = fmaf(q.y, cv.y, sgn * qr.y * sv.y) * scale;
    float k0 = fmaf(k.x, cv.x, sgn * kr.x * sv.x);
    float k1 = fmaf(k.y, cv.y, sgn * kr.y * sv.y);
    *(uint32_t*)&g_q16[(size_t)s * DIM + c] = pack_h2(q0, q1);
    *(uint32_t*)&g_k16[(size_t)s * DIM + c] = pack_h2(k0, k1);
}

// ---------------------------------------------------------------------------
// fp16 tensor-core flash attention. Block = 128 Q rows x (seg, head);
// 8 warps x 16 rows. Triple-buffered cp.async K/V (depth-2 prefetch);
// K via ldmatrix, V via ldmatrix.trans.  Softmax in exp2 domain with
// packed h2exp2 — results ARE the fp16 P fragments (halved MUFU load).
// ---------------------------------------------------------------------------
#define KVLD 88                            // K/V smem row stride (halves)
#define KVBUF_BYTES (64 * KVLD * 2)        // 11264
#define NBUF 3
#define ATT_SMEM (2 * NBUF * KVBUF_BYTES)  // 67584

__global__ __launch_bounds__(256, 2) void attn_f16()
{
    extern __shared__ __half asmem[];
    const uint32_t Ks_base = smem_addr_u32(asmem);
    const uint32_t Vs_base = Ks_base + NBUF * KVBUF_BYTES;

    const int tid = threadIdx.x;
    const int lane = tid & 31;
    const int w = tid >> 5;
    const int r = lane >> 2;
    const int cq = lane & 3;

    const int qb = blockIdx.x;
    const int h = blockIdx.y;
    const int seg = blockIdx.z;
    const int qrow = seg * SEGLEN + qb * 128 + w * 16;
    const int hoff = h * DH;

#define AISSUE(kvtv, buf) do {                                               \
    const int _tb = seg * SEGLEN + (kvtv) * 64;                              \
    for (int _c = tid; _c < 640; _c += 256) {                                \
        int _row = _c / 10, _c16 = _c - _row * 10;                           \
        uint32_t _kd = Ks_base + (buf) * KVBUF_BYTES + _row * (KVLD * 2) + _c16 * 16; \
        uint32_t _vd = Vs_base + (buf) * KVBUF_BYTES + _row * (KVLD * 2) + _c16 * 16; \
        const __half* _kp = g_k16 + (size_t)(_tb + _row) * DIM + hoff + _c16 * 8; \
        const __half* _vp = g_qkv16 + (size_t)(_tb + _row) * DIM3 + 2 * DIM + hoff + _c16 * 8; \
        asm volatile(                                                        \
            "cp.async.cg.shared.global [%0], [%1], 16;\n\t"                  \
            "cp.async.cg.shared.global [%2], [%3], 16;\n\t"                  \
            :: "r"(_kd), "l"(_kp), "r"(_vd), "l"(_vp) : "memory");           \
    }                                                                        \
    asm volatile("cp.async.commit_group;" ::: "memory");                     \
} while (0)

    // Q fragments: 5 k-steps of 16 halves
    uint32_t qa[5][4];
    {
        const __half* Qb = g_q16 + (size_t)qrow * DIM + hoff;
#pragma unroll
        for (int ks = 0; ks < 5; ks++) {
            qa[ks][0] = *(const uint32_t*)(Qb + (size_t)r * DIM + ks * 16 + 2 * cq);
            qa[ks][1] = *(const uint32_t*)(Qb + (size_t)(r + 8) * DIM + ks * 16 + 2 * cq);
            qa[ks][2] = *(const uint32_t*)(Qb + (size_t)r * DIM + ks * 16 + 8 + 2 * cq);
            qa[ks][3] = *(const uint32_t*)(Qb + (size_t)(r + 8) * DIM + ks * 16 + 8 + 2 * cq);
        }
    }

    float m0 = -1e30f, m1 = -1e30f, l0 = 0.f, l1 = 0.f;
    float oacc[10][4];
#pragma unroll
    for (int v = 0; v < 10; v++)
#pragma unroll
        for (int c = 0; c < 4; c++) oacc[v][c] = 0.f;

    // ldmatrix lane offsets (bytes within a buffer)
    const uint32_t kb_off = ((uint32_t)((lane & 7) + ((lane >> 4) << 3)) * KVLD +
                            (((lane >> 3) & 1) << 3)) * 2;
    const uint32_t vb_off = ((uint32_t)((lane & 7) + (((lane >> 3) & 1) << 3)) * KVLD +
                            (((lane >> 4) & 1) << 3)) * 2;

    AISSUE(0, 0);
    AISSUE(1, 1);

    for (int kvt = 0; kvt < 16; kvt++) {
        const int buf = kvt % NBUF;
        asm volatile("cp.async.wait_group 1;" ::: "memory");
        __syncthreads();
        if (kvt + 2 < 16) AISSUE(kvt + 2, (kvt + 2) % NBUF);

        const uint32_t kbase = Ks_base + buf * KVBUF_BYTES + kb_off;
        const uint32_t vbase = Vs_base + buf * KVBUF_BYTES + vb_off;

        // S = Q K^T (scores already in log2 domain via Q scaling)
        float sc[8][4];
#pragma unroll
        for (int j = 0; j < 8; j++)
#pragma unroll
            for (int c = 0; c < 4; c++) sc[j][c] = 0.f;

#pragma unroll
        for (int ks = 0; ks < 5; ks++) {
            uint32_t bq[4][4];
#pragma unroll
            for (int jp = 0; jp < 4; jp++)
                ldsm_x4(bq[jp], kbase + (uint32_t)(jp * 16 * KVLD * 2) +
                                (uint32_t)(ks * 32));
#pragma unroll
            for (int jp = 0; jp < 4; jp++) {
                mma_f16(sc[jp * 2], qa[ks], &bq[jp][0]);
                mma_f16(sc[jp * 2 + 1], qa[ks], &bq[jp][2]);
            }
        }

        // Online softmax in exp2 domain (C-frag layout: rows r / r+8)
        float mx0 = -1e30f, mx1 = -1e30f;
#pragma unroll
        for (int j = 0; j < 8; j++) {
            mx0 = fmaxf(mx0, fmaxf(sc[j][0], sc[j][1]));
            mx1 = fmaxf(mx1, fmaxf(sc[j][2], sc[j][3]));
        }
        mx0 = fmaxf(mx0, __shfl_xor_sync(0xffffffffu, mx0, 1));
        mx0 = fmaxf(mx0, __shfl_xor_sync(0xffffffffu, mx0, 2));
        mx1 = fmaxf(mx1, __shfl_xor_sync(0xffffffffu, mx1, 1));
        mx1 = fmaxf(mx1, __shfl_xor_sync(0xffffffffu, mx1, 2));
        const float nm0 = fmaxf(m0, mx0);
        const float nm1 = fmaxf(m1, mx1);
        const float corr0 = exp2f(m0 - nm0);
        const float corr1 = exp2f(m1 - nm1);
        m0 = nm0; m1 = nm1;

        // Packed exp2: p pairs come out as ready-to-use fp16 A-fragments.
        uint32_t p01[8], p23[8];
        float sum0 = 0.f, sum1 = 0.f;
#pragma unroll
        for (int j = 0; j < 8; j++) {
            __half2 a0 = __floats2half2_rn(sc[j][0] - nm0, sc[j][1] - nm0);
            __half2 a1 = __floats2half2_rn(sc[j][2] - nm1, sc[j][3] - nm1);
            __half2 e0 = h2exp2(a0);
            __half2 e1 = h2exp2(a1);
            p01[j] = *(uint32_t*)&e0;
            p23[j] = *(uint32_t*)&e1;
            float2 f0 = __half22float2(e0);
            float2 f1 = __half22float2(e1);
            sum0 += f0.x + f0.y;
            sum1 += f1.x + f1.y;
        }
        sum0 += __shfl_xor_sync(0xffffffffu, sum0, 1);
        sum0 += __shfl_xor_sync(0xffffffffu, sum0, 2);
        sum1 += __shfl_xor_sync(0xffffffffu, sum1, 1);
        sum1 += __shfl_xor_sync(0xffffffffu, sum1, 2);
        l0 = l0 * corr0 + sum0;
        l1 = l1 * corr1 + sum1;

#pragma unroll
        for (int v = 0; v < 10; v++) {
            oacc[v][0] *= corr0; oacc[v][1] *= corr0;
            oacc[v][2] *= corr1; oacc[v][3] *= corr1;
        }

        // O += P V
#pragma unroll
        for (int t = 0; t < 4; t++) {
            uint32_t pa[4];
            pa[0] = p01[2 * t];
            pa[1] = p23[2 * t];
            pa[2] = p01[2 * t + 1];
            pa[3] = p23[2 * t + 1];
#pragma unroll
            for (int vp = 0; vp < 5; vp++) {
                uint32_t bv[4];
                ldsm_x4_t(bv, vbase + (uint32_t)(t * 16 * KVLD * 2) +
                              (uint32_t)(vp * 32));
                mma_f16(oacc[2 * vp], pa, &bv[0]);
                mma_f16(oacc[2 * vp + 1], pa, &bv[2]);
            }
        }
    }
#undef AISSUE

    // Epilogue: fp16 out (proj GEMM input)
    const float inv0 = 1.f / l0;
    const float inv1 = 1.f / l1;
    __half* O0 = g_attn16 + (size_t)(qrow + r) * DIM + hoff;
    __half* O1 = g_attn16 + (size_t)(qrow + r + 8) * DIM + hoff;
#pragma unroll
    for (int v = 0; v < 10; v++) {
        *(uint32_t*)(O0 + v * 8 + 2 * cq) =
            pack_h2(oacc[v][0] * inv0, oacc[v][1] * inv0);
        *(uint32_t*)(O1 + v * 8 + 2 * cq) =
            pack_h2(oacc[v][2] * inv1, oacc[v][3] * inv1);
    }
}

// ---------------------------------------------------------------------------
extern "C" void kernel_launch(void* const* d_in, const int* in_sizes, int n_in,
                              void* d_out, int out_size)
{
    const float* hs     = (const float*)d_in[0];
    const float* cosp   = (const float*)d_in[1];
    const float* sinp   = (const float*)d_in[2];
    const float* qkv_w  = (const float*)d_in[3];
    const float* qkv_b  = (const float*)d_in[4];
    const float* proj_w = (const float*)d_in[5];
    const float* proj_b = (const float*)d_in[6];
    float* out = (float*)d_out;

    __half *qkv_p, *attn_p, *hs_p, *wq_p, *wp_p;
    cudaGetSymbolAddress((void**)&qkv_p, g_qkv16);
    cudaGetSymbolAddress((void**)&attn_p, g_attn16);
    cudaGetSymbolAddress((void**)&hs_p, g_hs16);
    cudaGetSymbolAddress((void**)&wq_p, g_wq16);
    cudaGetSymbolAddress((void**)&wp_p, g_wp16);

    cudaFuncSetAttribute(gemm_f16_pipe,
                         cudaFuncAttributeMaxDynamicSharedMemorySize, GEMM_SMEM);
    cudaFuncSetAttribute(attn_f16,
                         cudaFuncAttributeMaxDynamicSharedMemorySize, ATT_SMEM);

    // 0) Convert all GEMM inputs to fp16 (single launch)
    convert_all_kernel<<<(N4_ALL + 255) / 256, 256>>>(
        (const float4*)hs, (const float4*)qkv_w, (const float4*)proj_w,
        hs_p, wq_p, wp_p);

    // 1) QKV GEMM + bias (fp16 tensor cores), fp16 output
    dim3 g1(DIM3 / 128, S_TOK / 128);
    gemm_f16_pipe<<<g1, 256, GEMM_SMEM>>>(hs_p, wq_p, qkv_b, qkv_p, DIM3, 1);

    // 2) RoPE (folds softmax scale * log2e into Q), half2-vectorized
    int pairs = S_TOK * (DIM / 2);
    rope16_kernel<<<(pairs + 255) / 256, 256>>>(cosp, sinp);

    // 3) fp16 tensor-core flash attention (triple-buffered, exp2 softmax)
    dim3 g2(SEGLEN / 128, NH, NSEG);
    attn_f16<<<g2, 256, ATT_SMEM>>>();

    // 4) Output projection + bias (fp32 output)
    dim3 g3(DIM / 128, S_TOK / 128);
    gemm_f16_pipe<<<g3, 256, GEMM_SMEM>>>(attn_p, wp_p, proj_b, out, DIM, 0);
}

// round 17
// speedup vs baseline: 1.2793x; 1.0103x over previous
#include <cuda_runtime.h>
#include <cuda_fp16.h>
#include <cstdint>
#include <cstddef>

#define S_TOK 8192
#define DIM 1280
#define DIM3 3840
#define NH 16
#define DH 80
#define NSEG 8
#define SEGLEN 1024
#define GK 1280           // GEMM K (halves)
#define GBK 32            // GEMM k per tile (halves)
#define GNT (GK / GBK)    // 40 k-tiles

// Scratch (device globals: allocation-free per harness rules)
__device__ __half g_qkv16[S_TOK * DIM3];  // qkv result (fp16)
__device__ __half g_q16[S_TOK * DIM];     // roped Q * scale*log2e (fp16)
__device__ __half g_k16[S_TOK * DIM];     // roped K (fp16)
__device__ __half g_attn16[S_TOK * DIM];  // attention out (fp16)
__device__ __half g_hs16[S_TOK * DIM];    // fp16 hidden_states
__device__ __half g_wq16[DIM3 * DIM];     // fp16 qkv_w
__device__ __half g_wp16[DIM * DIM];      // fp16 proj_w

// ---------------------------------------------------------------------------
// helpers (baseline PTX, no arch-specific features)
// ---------------------------------------------------------------------------
__device__ __forceinline__ void mma_f16(float* c, const uint32_t* a, const uint32_t* b) {
    asm volatile(
        "mma.sync.aligned.m16n8k16.row.col.f32.f16.f16.f32 "
        "{%0,%1,%2,%3}, {%4,%5,%6,%7}, {%8,%9}, {%0,%1,%2,%3};"
        : "+f"(c[0]), "+f"(c[1]), "+f"(c[2]), "+f"(c[3])
        : "r"(a[0]), "r"(a[1]), "r"(a[2]), "r"(a[3]), "r"(b[0]), "r"(b[1]));
}

__device__ __forceinline__ void ldsm_x4(uint32_t* r, uint32_t addr) {
    asm volatile(
        "ldmatrix.sync.aligned.m8n8.x4.shared.b16 {%0,%1,%2,%3}, [%4];"
        : "=r"(r[0]), "=r"(r[1]), "=r"(r[2]), "=r"(r[3]) : "r"(addr));
}

__device__ __forceinline__ void ldsm_x4_t(uint32_t* r, uint32_t addr) {
    asm volatile(
        "ldmatrix.sync.aligned.m8n8.x4.trans.shared.b16 {%0,%1,%2,%3}, [%4];"
        : "=r"(r[0]), "=r"(r[1]), "=r"(r[2]), "=r"(r[3]) : "r"(addr));
}

__device__ __forceinline__ uint32_t smem_addr_u32(const void* p) {
    return (uint32_t)__cvta_generic_to_shared(p);
}

__device__ __forceinline__ uint32_t pack_h2(float a, float b) {
    __half2 h = __floats2half2_rn(a, b);
    return *(uint32_t*)&h;
}

// ---------------------------------------------------------------------------
// Merged fp32 -> fp16 convert for hs, qkv_w, proj_w (one launch)
// ---------------------------------------------------------------------------
#define N4_HS   (S_TOK * DIM / 4)
#define N4_WQ   (DIM3 * DIM / 4)
#define N4_WP   (DIM * DIM / 4)
#define N4_ALL  (N4_HS + N4_WQ + N4_WP)

__global__ void convert_all_kernel(const float4* __restrict__ hs,
                                   const float4* __restrict__ wq,
                                   const float4* __restrict__ wp,
                                   __half* __restrict__ hs16,
                                   __half* __restrict__ wq16,
                                   __half* __restrict__ wp16)
{
    int i = blockIdx.x * blockDim.x + threadIdx.x;
    if (i >= N4_ALL) return;
    const float4* src;
    __half* dst;
    int k;
    if (i < N4_HS) {
        src = hs; dst = hs16; k = i;
    } else if (i < N4_HS + N4_WQ) {
        src = wq; dst = wq16; k = i - N4_HS;
    } else {
        src = wp; dst = wp16; k = i - N4_HS - N4_WQ;
    }
    float4 v = src[k];
    uint2 o;
    o.x = pack_h2(v.x, v.y);
    o.y = pack_h2(v.z, v.w);
    *(uint2*)(dst + (size_t)k * 4) = o;
}

// ---------------------------------------------------------------------------
// fp16 tensor-core GEMM (NT): C[M,N] = A[M,1280] @ B[N,1280]^T + bias[N]
// BM=BN=128, BK=32 halves, 256 threads (8 warps, 2Mx4N, warp tile 64x32).
// 4-stage cp.async pipeline; fragments via ldmatrix, batch-then-compute.
// (exact R11/R15 configuration — benched best)
// ---------------------------------------------------------------------------
#define GLDH 40                            // smem row stride in halves
#define STAGES 4
#define STAGE_BYTES (128 * GLDH * 2)       // 10240
#define GEMM_SMEM (STAGES * 2 * STAGE_BYTES)  // 81920

__global__ __launch_bounds__(256, 2) void gemm_f16_pipe(
    const __half* __restrict__ A, const __half* __restrict__ B,
    const float* __restrict__ bias, void* __restrict__ Cout,
    int N, int half_out)
{
    extern __shared__ __half smp[];
    __half* As = smp;                                 // [STAGES][128][GLDH]
    __half* Bs = smp + STAGES * 128 * GLDH;

    const int tid = threadIdx.x;
    const int lane = tid & 31;
    const int wid = tid >> 5;
    const int wm = (wid & 1) * 64;
    const int wn = (wid >> 1) * 32;
    const int bm = blockIdx.y * 128;
    const int bn = blockIdx.x * 128;

    const int lrow = tid >> 1;            // 0..127
    const int lhh = (tid & 1) * 16;       // halves 0 or 16
    const __half* Ag = A + (size_t)(bm + lrow) * GK + lhh;
    const __half* Bg = B + (size_t)(bn + lrow) * GK + lhh;

    const uint32_t As_base = smem_addr_u32(As);
    const uint32_t Bs_base = smem_addr_u32(Bs);
    const uint32_t sA = As_base + (uint32_t)(lrow * GLDH + lhh) * 2;
    const uint32_t sB = Bs_base + (uint32_t)(lrow * GLDH + lhh) * 2;

    // ldmatrix lane offsets (bytes within a stage)
    const uint32_t a_off = ((uint32_t)(wm + (lane & 15)) * GLDH +
                            ((lane >> 4) << 3)) * 2;
    const uint32_t b_off = ((uint32_t)(wn + (lane & 7) + ((lane >> 4) << 3)) * GLDH +
                            (((lane >> 3) & 1) << 3)) * 2;

    float acc[4][4][4];
#pragma unroll
    for (int i = 0; i < 4; i++)
#pragma unroll
        for (int j = 0; j < 4; j++)
#pragma unroll
            for (int c = 0; c < 4; c++) acc[i][j][c] = 0.f;

#define ISSUE(ktv) do {                                                      \
    const int _st = (ktv) % STAGES;                                          \
    const __half* _ap = Ag + (ktv) * GBK;                                    \
    const __half* _bp = Bg + (ktv) * GBK;                                    \
    uint32_t _da = sA + _st * STAGE_BYTES;                                   \
    uint32_t _db = sB + _st * STAGE_BYTES;                                   \
    asm volatile(                                                            \
        "cp.async.cg.shared.global [%0], [%1], 16;\n\t"                      \
        "cp.async.cg.shared.global [%2], [%3], 16;\n\t"                      \
        "cp.async.cg.shared.global [%4], [%5], 16;\n\t"                      \
        "cp.async.cg.shared.global [%6], [%7], 16;\n\t"                      \
        "cp.async.commit_group;"                                             \
        :: "r"(_da), "l"(_ap), "r"(_da + 16), "l"(_ap + 8),                  \
           "r"(_db), "l"(_bp), "r"(_db + 16), "l"(_bp + 8) : "memory");      \
} while (0)

#pragma unroll
    for (int s = 0; s < STAGES - 1; s++) ISSUE(s);

    for (int kt = 0; kt < GNT; ++kt) {
        const int st = kt % STAGES;
        asm volatile("cp.async.wait_group %0;" :: "n"(STAGES - 2));
        __syncthreads();
        if (kt + STAGES - 1 < GNT) ISSUE(kt + STAGES - 1);

        const uint32_t a_base = As_base + st * STAGE_BYTES + a_off;
        const uint32_t b_base = Bs_base + st * STAGE_BYTES + b_off;

        // Batch ALL fragment loads (both k-steps), then all MMAs.
        uint32_t af[2][4][4], bq[2][2][4];
#pragma unroll
        for (int ks = 0; ks < 2; ++ks) {
            const uint32_t kcb = ks * 16 * 2;
#pragma unroll
            for (int i = 0; i < 4; i++)
                ldsm_x4(af[ks][i], a_base + (uint32_t)(i * 16 * GLDH * 2) + kcb);
#pragma unroll
            for (int jp = 0; jp < 2; jp++)
                ldsm_x4(bq[ks][jp], b_base + (uint32_t)(jp * 16 * GLDH * 2) + kcb);
        }
#pragma unroll
        for (int ks = 0; ks < 2; ++ks)
#pragma unroll
            for (int i = 0; i < 4; i++)
#pragma unroll
                for (int j = 0; j < 4; j++)
                    mma_f16(acc[i][j], af[ks][i], &bq[ks][j >> 1][(j & 1) * 2]);
    }
#undef ISSUE

    const int r = lane >> 2;
    const int cq = lane & 3;
#pragma unroll
    for (int i = 0; i < 4; i++) {
        const int row0 = bm + wm + i * 16 + r;
#pragma unroll
        for (int j = 0; j < 4; j++) {
            const int col = bn + wn + j * 8 + cq * 2;
            const float b0 = bias[col], b1 = bias[col + 1];
            if (half_out) {
                __half* C16 = (__half*)Cout;
                *(uint32_t*)(C16 + (size_t)row0 * N + col) =
                    pack_h2(acc[i][j][0] + b0, acc[i][j][1] + b1);
                *(uint32_t*)(C16 + (size_t)(row0 + 8) * N + col) =
                    pack_h2(acc[i][j][2] + b0, acc[i][j][3] + b1);
            } else {
                float* C32 = (float*)Cout;
                float2 v;
                v.x = acc[i][j][0] + b0; v.y = acc[i][j][1] + b1;
                *(float2*)(C32 + (size_t)row0 * N + col) = v;
                v.x = acc[i][j][2] + b0; v.y = acc[i][j][3] + b1;
                *(float2*)(C32 + (size_t)(row0 + 8) * N + col) = v;
            }
        }
    }
}

// ---------------------------------------------------------------------------
// RoPE on fp16 qkv (half2-vectorized): q <- (q*cos + rot(q)*sin)*scale*log2e,
// k <- k*cos + rot(k)*sin.  log2e folded into Q so attention can use exp2.
// ---------------------------------------------------------------------------
__global__ void rope16_kernel(const float* __restrict__ cosp,
                              const float* __restrict__ sinp)
{
    int idx = blockIdx.x * blockDim.x + threadIdx.x;   // pair index
    if (idx >= S_TOK * (DIM / 2)) return;
    int s = idx / (DIM / 2);
    int c = (idx - s * (DIM / 2)) * 2;
    int d = c % DH;
    float2 cv = *(const float2*)&cosp[s * DH + d];
    float2 sv = *(const float2*)&sinp[s * DH + d];
    const __half* row = g_qkv16 + (size_t)s * DIM3;
    __half2 qh = *(const __half2*)&row[c];
    __half2 kh = *(const __half2*)&row[DIM + c];
    __half2 qrh, krh;
    float sgn;
    if (d < DH / 2) {
        qrh = *(const __half2*)&row[c + DH / 2];
        krh = *(const __half2*)&row[DIM + c + DH / 2];
        sgn = -1.f;
    } else {
        qrh = *(const __half2*)&row[c - DH / 2];
        krh = *(const __half2*)&row[DIM + c - DH / 2];
        sgn = 1.f;
    }
    float2 q = __half22float2(qh), k = __half22float2(kh);
    float2 qr = __half22float2(qrh), kr = __half22float2(krh);
    // 1/sqrt(80) * log2(e)  (exp2-domain softmax)
    const float scale = 0.11180339887498949f * 1.4426950408889634f;
    float q0 = fmaf(q.x, cv.x, sgn * qr.x * sv.x) * scale;
    float q1 = fmaf(q.y, cv.y, sgn * qr.y * sv.y) * scale;
    float k0 = fmaf(k.x, cv.x, sgn * kr.x * sv.x);
    float k1 = fmaf(k.y, cv.y, sgn * kr.y * sv.y);
    *(uint32_t*)&g_q16[(size_t)s * DIM + c] = pack_h2(q0, q1);
    *(uint32_t*)&g_k16[(size_t)s * DIM + c] = pack_h2(k0, k1);
}

// ---------------------------------------------------------------------------
// fp16 tensor-core flash attention. Block = 128 Q rows x (seg, head);
// 8 warps x 16 rows. Triple-buffered cp.async K/V (depth-2 prefetch);
// K via ldmatrix, V via ldmatrix.trans. exp2-domain softmax with packed
// h2exp2.  Softmax denominator computed BY THE TENSOR CORE via a constant
// ones-column at V col 80 (pad region, never touched by cp.async fills):
// O column 80 accumulates sum(P) with corr-rescaling applied for free.
// ---------------------------------------------------------------------------
#define KVLD 88                            // K/V smem row stride (halves)
#define KVBUF_BYTES (64 * KVLD * 2)        // 11264
#define NBUF 3
#define ATT_SMEM (2 * NBUF * KVBUF_BYTES + 1024)  // +pad for vp=5 ldsm overread

__global__ __launch_bounds__(256, 2) void attn_f16()
{
    extern __shared__ __half asmem[];
    const uint32_t Ks_base = smem_addr_u32(asmem);
    const uint32_t Vs_base = Ks_base + NBUF * KVBUF_BYTES;

    const int tid = threadIdx.x;
    const int lane = tid & 31;
    const int w = tid >> 5;
    const int r = lane >> 2;
    const int cq = lane & 3;

    const int qb = blockIdx.x;
    const int h = blockIdx.y;
    const int seg = blockIdx.z;
    const int qrow = seg * SEGLEN + qb * 128 + w * 16;
    const int hoff = h * DH;

#define AISSUE(kvtv, buf) do {                                               \
    const int _tb = seg * SEGLEN + (kvtv) * 64;                              \
    for (int _c = tid; _c < 640; _c += 256) {                                \
        int _row = _c / 10, _c16 = _c - _row * 10;                           \
        uint32_t _kd = Ks_base + (buf) * KVBUF_BYTES + _row * (KVLD * 2) + _c16 * 16; \
        uint32_t _vd = Vs_base + (buf) * KVBUF_BYTES + _row * (KVLD * 2) + _c16 * 16; \
        const __half* _kp = g_k16 + (size_t)(_tb + _row) * DIM + hoff + _c16 * 8; \
        const __half* _vp = g_qkv16 + (size_t)(_tb + _row) * DIM3 + 2 * DIM + hoff + _c16 * 8; \
        asm volatile(                                                        \
            "cp.async.cg.shared.global [%0], [%1], 16;\n\t"                  \
            "cp.async.cg.shared.global [%2], [%3], 16;\n\t"                  \
            :: "r"(_kd), "l"(_kp), "r"(_vd), "l"(_vp) : "memory");           \
    }                                                                        \
    asm volatile("cp.async.commit_group;" ::: "memory");                     \
} while (0)

    // One-time init: ones-column at V col 80, zeros 81..87 (all 3 buffers).
    // cp.async fills only write cols 0..79, so this persists across tiles.
    {
        __half* vpad = asmem + NBUF * 64 * KVLD;   // start of V region
        const uint4 ones = make_uint4(0x00003C00u, 0u, 0u, 0u);
        for (int i = tid; i < NBUF * 64; i += 256)
            *(uint4*)(vpad + (size_t)i * KVLD + 80) = ones;
    }

    // Q fragments: 5 k-steps of 16 halves
    uint32_t qa[5][4];
    {
        const __half* Qb = g_q16 + (size_t)qrow * DIM + hoff;
#pragma unroll
        for (int ks = 0; ks < 5; ks++) {
            qa[ks][0] = *(const uint32_t*)(Qb + (size_t)r * DIM + ks * 16 + 2 * cq);
            qa[ks][1] = *(const uint32_t*)(Qb + (size_t)(r + 8) * DIM + ks * 16 + 2 * cq);
            qa[ks][2] = *(const uint32_t*)(Qb + (size_t)r * DIM + ks * 16 + 8 + 2 * cq);
            qa[ks][3] = *(const uint32_t*)(Qb + (size_t)(r + 8) * DIM + ks * 16 + 8 + 2 * cq);
        }
    }

    float m0 = -1e30f, m1 = -1e30f;
    float oacc[11][4];   // [10] = denominator column (col 80)
#pragma unroll
    for (int v = 0; v < 11; v++)
#pragma unroll
        for (int c = 0; c < 4; c++) oacc[v][c] = 0.f;

    // ldmatrix lane offsets (bytes within a buffer)
    const uint32_t kb_off = ((uint32_t)((lane & 7) + ((lane >> 4) << 3)) * KVLD +
                            (((lane >> 3) & 1) << 3)) * 2;
    const uint32_t vb_off = ((uint32_t)((lane & 7) + (((lane >> 3) & 1) << 3)) * KVLD +
                            (((lane >> 4) & 1) << 3)) * 2;

    AISSUE(0, 0);
    AISSUE(1, 1);

    for (int kvt = 0; kvt < 16; kvt++) {
        const int buf = kvt % NBUF;
        asm volatile("cp.async.wait_group 1;" ::: "memory");
        __syncthreads();   // also publishes the one-time ones-column STS
        if (kvt + 2 < 16) AISSUE(kvt + 2, (kvt + 2) % NBUF);

        const uint32_t kbase = Ks_base + buf * KVBUF_BYTES + kb_off;
        const uint32_t vbase = Vs_base + buf * KVBUF_BYTES + vb_off;

        // S = Q K^T (scores already in log2 domain via Q scaling)
        float sc[8][4];
#pragma unroll
        for (int j = 0; j < 8; j++)
#pragma unroll
            for (int c = 0; c < 4; c++) sc[j][c] = 0.f;

#pragma unroll
        for (int ks = 0; ks < 5; ks++) {
            uint32_t bq[4][4];
#pragma unroll
            for (int jp = 0; jp < 4; jp++)
                ldsm_x4(bq[jp], kbase + (uint32_t)(jp * 16 * KVLD * 2) +
                                (uint32_t)(ks * 32));
#pragma unroll
            for (int jp = 0; jp < 4; jp++) {
                mma_f16(sc[jp * 2], qa[ks], &bq[jp][0]);
                mma_f16(sc[jp * 2 + 1], qa[ks], &bq[jp][2]);
            }
        }

        // Online softmax max (C-frag layout: rows r / r+8)
        float mx0 = -1e30f, mx1 = -1e30f;
#pragma unroll
        for (int j = 0; j < 8; j++) {
            mx0 = fmaxf(mx0, fmaxf(sc[j][0], sc[j][1]));
            mx1 = fmaxf(mx1, fmaxf(sc[j][2], sc[j][3]));
        }
        mx0 = fmaxf(mx0, __shfl_xor_sync(0xffffffffu, mx0, 1));
        mx0 = fmaxf(mx0, __shfl_xor_sync(0xffffffffu, mx0, 2));
        mx1 = fmaxf(mx1, __shfl_xor_sync(0xffffffffu, mx1, 1));
        mx1 = fmaxf(mx1, __shfl_xor_sync(0xffffffffu, mx1, 2));
        const float nm0 = fmaxf(m0, mx0);
        const float nm1 = fmaxf(m1, mx1);
        const float corr0 = exp2f(m0 - nm0);
        const float corr1 = exp2f(m1 - nm1);
        m0 = nm0; m1 = nm1;

        // Packed exp2: results ARE the fp16 P fragments (no sums needed —
        // the ones-column MMA accumulates the denominator).
        uint32_t p01[8], p23[8];
#pragma unroll
        for (int j = 0; j < 8; j++) {
            __half2 a0 = __floats2half2_rn(sc[j][0] - nm0, sc[j][1] - nm0);
            __half2 a1 = __floats2half2_rn(sc[j][2] - nm1, sc[j][3] - nm1);
            __half2 e0 = h2exp2(a0);
            __half2 e1 = h2exp2(a1);
            p01[j] = *(uint32_t*)&e0;
            p23[j] = *(uint32_t*)&e1;
        }

#pragma unroll
        for (int v = 0; v < 11; v++) {
            oacc[v][0] *= corr0; oacc[v][1] *= corr0;
            oacc[v][2] *= corr1; oacc[v][3] *= corr1;
        }

        // O += P V  (vp=0..4 data, then the ones-column tile for the denom)
#pragma unroll
        for (int t = 0; t < 4; t++) {
            uint32_t pa[4];
            pa[0] = p01[2 * t];
            pa[1] = p23[2 * t];
            pa[2] = p01[2 * t + 1];
            pa[3] = p23[2 * t + 1];
#pragma unroll
            for (int vp = 0; vp < 5; vp++) {
                uint32_t bv[4];
                ldsm_x4_t(bv, vbase + (uint32_t)(t * 16 * KVLD * 2) +
                              (uint32_t)(vp * 32));
                mma_f16(oacc[2 * vp], pa, &bv[0]);
                mma_f16(oacc[2 * vp + 1], pa, &bv[2]);
            }
            {
                uint32_t bv[4];
                ldsm_x4_t(bv, vbase + (uint32_t)(t * 16 * KVLD * 2) + 160);
                mma_f16(oacc[10], pa, &bv[0]);   // cols 80..87 (ones at 80)
            }
        }
    }
#undef AISSUE

    // Epilogue: denominator lives in O col 80 => cq==0 lane of each quad.
    const float l0 = __shfl_sync(0xffffffffu, oacc[10][0], lane & 28);
    const float l1 = __shfl_sync(0xffffffffu, oacc[10][2], lane & 28);
    const float inv0 = 1.f / l0;
    const float inv1 = 1.f / l1;
    __half* O0 = g_attn16 + (size_t)(qrow + r) * DIM + hoff;
    __half* O1 = g_attn16 + (size_t)(qrow + r + 8) * DIM + hoff;
#pragma unroll
    for (int v = 0; v < 10; v++) {
        *(uint32_t*)(O0 + v * 8 + 2 * cq) =
            pack_h2(oacc[v][0] * inv0, oacc[v][1] * inv0);
        *(uint32_t*)(O1 + v * 8 + 2 * cq) =
            pack_h2(oacc[v][2] * inv1, oacc[v][3] * inv1);
    }
}

// ---------------------------------------------------------------------------
extern "C" void kernel_launch(void* const* d_in, const int* in_sizes, int n_in,
                              void* d_out, int out_size)
{
    const float* hs     = (const float*)d_in[0];
    const float* cosp   = (const float*)d_in[1];
    const float* sinp   = (const float*)d_in[2];
    const float* qkv_w  = (const float*)d_in[3];
    const float* qkv_b  = (const float*)d_in[4];
    const float* proj_w = (const float*)d_in[5];
    const float* proj_b = (const float*)d_in[6];
    float* out = (float*)d_out;

    __half *qkv_p, *attn_p, *hs_p, *wq_p, *wp_p;
    cudaGetSymbolAddress((void**)&qkv_p, g_qkv16);
    cudaGetSymbolAddress((void**)&attn_p, g_attn16);
    cudaGetSymbolAddress((void**)&hs_p, g_hs16);
    cudaGetSymbolAddress((void**)&wq_p, g_wq16);
    cudaGetSymbolAddress((void**)&wp_p, g_wp16);

    cudaFuncSetAttribute(gemm_f16_pipe,
                         cudaFuncAttributeMaxDynamicSharedMemorySize, GEMM_SMEM);
    cudaFuncSetAttribute(attn_f16,
                         cudaFuncAttributeMaxDynamicSharedMemorySize, ATT_SMEM);

    // 0) Convert all GEMM inputs to fp16 (single launch)
    convert_all_kernel<<<(N4_ALL + 255) / 256, 256>>>(
        (const float4*)hs, (const float4*)qkv_w, (const float4*)proj_w,
        hs_p, wq_p, wp_p);

    // 1) QKV GEMM + bias (fp16 tensor cores), fp16 output
    dim3 g1(DIM3 / 128, S_TOK / 128);
    gemm_f16_pipe<<<g1, 256, GEMM_SMEM>>>(hs_p, wq_p, qkv_b, qkv_p, DIM3, 1);

    // 2) RoPE (folds softmax scale * log2e into Q), half2-vectorized
    int pairs = S_TOK * (DIM / 2);
    rope16_kernel<<<(pairs + 255) / 256, 256>>>(cosp, sinp);

    // 3) fp16 tensor-core flash attention (triple-buffered, exp2 softmax,
    //    tensor-core denominator)
    dim3 g2(SEGLEN / 128, NH, NSEG);
    attn_f16<<<g2, 256, ATT_SMEM>>>();

    // 4) Output projection + bias (fp32 output)
    dim3 g3(DIM / 128, S_TOK / 128);
    gemm_f16_pipe<<<g3, 256, GEMM_SMEM>>>(attn_p, wp_p, proj_b, out, DIM, 0);
}